// round 7
// baseline (speedup 1.0000x reference)
#include <cuda_runtime.h>
#include <cuda_bf16.h>
#include <math.h>

#define Bn 32
#define Tn 2048
#define In 512
#define Hn 512
#define Ln 4
#define Gn 2048   // 4*H

// ---------------- phase A (xg pre-GEMM) config ----------------
#define GT 256
#define TR 128
#define TK 32
#define WPAD 132
#define ZPAD 132
#define GEMM_SMEM ((2*TK*WPAD + 2*TK*ZPAD) * 4)

// ---------------- recurrence config (batch groups, dataflow sync) ----------------
#define NCTA 128
#define RTPB 512
#define NGRP 4          // batch groups
#define GCTA 32         // CTAs (producers) per group
#define GB 8            // batches per group
#define CROWS 64        // gate rows per CTA (4 gates x 16 units)
#define CUNITS 16
#define KSn 8           // K-split ways (64 wide each)
#define WPITCH 516      // floats; row stride (fat-bank coprime via row-assignment)
#define ZPITCH 516
#define REC_SMEM ((CROWS*WPITCH + GB*ZPITCH + KSn*CROWS*GB) * 4)

// Static scratch
__device__ float g_xg[(size_t)Tn * Gn * Bn];       // [t][gate_row][b]
__device__ float g_hT[2][(size_t)Tn * Bn * Hn];    // ping-pong [t][b][j]
__device__ unsigned g_flags[NCTA];

__global__ void init_kernel() {
  if (threadIdx.x < NCTA) g_flags[threadIdx.x] = 0u;
}

// ============ Phase A: xg[t][gr][b] = sum_i W[gr][i]*inp + bias ============
// mode 0: inp = x, layout (B, T, I). mode 1: inp = g_hT[hin], layout [t][b][i].
__global__ void __launch_bounds__(GT, 2) xg_gemm_kernel(
    const float* __restrict__ W,
    const float* __restrict__ bih, const float* __restrict__ bhh,
    const float* __restrict__ x, int mode, int hin)
{
  extern __shared__ float sm[];
  float* Ws = sm;                  // [2][TK][WPAD]
  float* Zs = sm + 2 * TK * WPAD;  // [2][TK][ZPAD]

  const float* inp = mode ? g_hT[hin] : x;
  const int tid = threadIdx.x;
  const int t0 = blockIdx.x * 4;
  const int r0 = blockIdx.y * TR;
  const int trow = tid >> 4;
  const int tcol = tid & 15;

  float acc[8][8];
#pragma unroll
  for (int i = 0; i < 8; i++)
#pragma unroll
    for (int j = 0; j < 8; j++) acc[i][j] = 0.f;

  float4 wr[4], zr[4];

  auto ldg_chunk = [&](int kc) {
#pragma unroll
    for (int j = 0; j < 4; j++) {
      int idx = tid * 4 + j;
      int row = idx >> 3, kq = idx & 7;
      wr[j] = *reinterpret_cast<const float4*>(W + (size_t)(r0 + row) * In + kc + kq * 4);
    }
#pragma unroll
    for (int j = 0; j < 4; j++) {
      int idx = tid * 4 + j;
      int ki = idx & 7, tt = (idx >> 3) & 3, b = idx >> 5;
      size_t base = mode ? ((size_t)(t0 + tt) * Bn + b) * In
                         : ((size_t)b * Tn + t0 + tt) * In;
      zr[j] = *reinterpret_cast<const float4*>(inp + base + kc + ki * 4);
    }
  };

  auto sts_chunk = [&](int buf) {
    float* Wb = Ws + buf * TK * WPAD;
    float* Zb = Zs + buf * TK * ZPAD;
#pragma unroll
    for (int j = 0; j < 4; j++) {
      int idx = tid * 4 + j;
      int row = idx >> 3, kq = idx & 7;
      Wb[(kq * 4 + 0) * WPAD + row] = wr[j].x;
      Wb[(kq * 4 + 1) * WPAD + row] = wr[j].y;
      Wb[(kq * 4 + 2) * WPAD + row] = wr[j].z;
      Wb[(kq * 4 + 3) * WPAD + row] = wr[j].w;
    }
#pragma unroll
    for (int j = 0; j < 4; j++) {
      int idx = tid * 4 + j;
      int ki = idx & 7, tt = (idx >> 3) & 3, b = idx >> 5;
      Zb[(ki * 4 + 0) * ZPAD + tt * 32 + b] = zr[j].x;
      Zb[(ki * 4 + 1) * ZPAD + tt * 32 + b] = zr[j].y;
      Zb[(ki * 4 + 2) * ZPAD + tt * 32 + b] = zr[j].z;
      Zb[(ki * 4 + 3) * ZPAD + tt * 32 + b] = zr[j].w;
    }
  };

  auto compute = [&](int buf) {
    const float* Wb = Ws + buf * TK * WPAD;
    const float* Zb = Zs + buf * TK * ZPAD;
#pragma unroll 8
    for (int kk = 0; kk < TK; kk++) {
      float4 wa = *reinterpret_cast<const float4*>(Wb + kk * WPAD + trow * 8);
      float4 wb2 = *reinterpret_cast<const float4*>(Wb + kk * WPAD + trow * 8 + 4);
      float4 za = *reinterpret_cast<const float4*>(Zb + kk * ZPAD + tcol * 8);
      float4 zb2 = *reinterpret_cast<const float4*>(Zb + kk * ZPAD + tcol * 8 + 4);
      float w8[8] = {wa.x, wa.y, wa.z, wa.w, wb2.x, wb2.y, wb2.z, wb2.w};
      float z8[8] = {za.x, za.y, za.z, za.w, zb2.x, zb2.y, zb2.z, zb2.w};
#pragma unroll
      for (int i = 0; i < 8; i++)
#pragma unroll
        for (int j = 0; j < 8; j++)
          acc[i][j] = fmaf(w8[i], z8[j], acc[i][j]);
    }
  };

  const int NCH = In / TK;   // 16
  ldg_chunk(0);
  sts_chunk(0);
  __syncthreads();
  ldg_chunk(TK);
  for (int c = 0; c < NCH; c++) {
    int buf = c & 1;
    if (c + 1 < NCH) sts_chunk(buf ^ 1);
    if (c + 2 < NCH) ldg_chunk((c + 2) * TK);
    compute(buf);
    __syncthreads();
  }

#pragma unroll
  for (int i = 0; i < 8; i++) {
    int row = r0 + trow * 8 + i;
    float bv = __ldg(bih + row) + __ldg(bhh + row);
    int tt = tcol >> 2;
    int b0 = (tcol & 3) * 8;
    float* dst = g_xg + ((size_t)(t0 + tt) * Gn + row) * Bn + b0;
    float4 v0 = make_float4(acc[i][0] + bv, acc[i][1] + bv, acc[i][2] + bv, acc[i][3] + bv);
    float4 v1 = make_float4(acc[i][4] + bv, acc[i][5] + bv, acc[i][6] + bv, acc[i][7] + bv);
    *reinterpret_cast<float4*>(dst) = v0;
    *reinterpret_cast<float4*>(dst + 4) = v1;
  }
}

__device__ __forceinline__ float fsigm(float v) {
  return __fdividef(1.f, 1.f + __expf(-v));
}
__device__ __forceinline__ float ftanh(float v) {
  float e = __expf(-2.f * v);
  return __fdividef(1.f - e, 1.f + e);
}

// ============ Recurrence: dataflow (per-producer flag) sync, no grid barrier ======
__global__ void __launch_bounds__(RTPB, 1) lstm_rec_kernel(
    const float* __restrict__ h0, const float* __restrict__ c0,
    const float* __restrict__ Whh,
    float* __restrict__ out, int l, int hsel)
{
  extern __shared__ float smem[];
  float* Wsh = smem;                       // [64][WPITCH]
  float* zsh = Wsh + CROWS * WPITCH;       // [8][ZPITCH]   z[b][j]
  float* pre = zsh + GB * ZPITCH;          // [KSn][64][8]

  const int tid = threadIdx.x;
  const int ct = blockIdx.x;
  const int grp = ct >> 5;                 // batch group 0..3
  const int cl = ct & 31;                  // CTA within group
  // GEMM mapping: ks = K-slice (const per warp-pair), rg row-group, bp batch
  const int ks = tid >> 6;                 // 0..7  (64-wide K slice)
  const int rg = (tid >> 2) & 15;          // rows rg, rg+16, rg+32, rg+48
  const int bp = tid & 3;                  // batches bp, bp+4
  // gates mapping (tid < 128): (unit, local batch)
  const int u = tid >> 3;                  // 0..15
  const int bl = tid & 7;                  // 0..7
  const int gb = grp * GB + bl;            // global batch
  const int unit = cl * CUNITS + u;        // global hidden unit
  // staging mapping: warp handles producers 2w, 2w+1
  const int wrp = tid >> 5;
  const int lane = tid & 31;

  float* hout = g_hT[hsel];
  const float* xg = g_xg;
  float4* zsh4 = reinterpret_cast<float4*>(zsh);
  const int ZP4 = ZPITCH / 4;              // 129

  // load Whh slice: local row rr = q*16 + uu -> global row q*512 + cl*16 + uu
  for (int idx = tid; idx < CROWS * (Hn / 4); idx += RTPB) {
    int rr = idx >> 7, kk = idx & 127;
    int q = rr >> 4, uu = rr & 15;
    int gr = q * Hn + cl * CUNITS + uu;
    *reinterpret_cast<float4*>(Wsh + rr * WPITCH + kk * 4) =
        *reinterpret_cast<const float4*>(Whh + (size_t)gr * Hn + kk * 4);
  }
  float c = (tid < 128) ? c0[(size_t)l * Bn * Hn + (size_t)gb * Hn + unit] : 0.f;

  const unsigned base = (unsigned)(l * Tn);
  const unsigned* gflags = g_flags + (grp << 5);
  const int p0 = 2 * wrp, p1 = p0 + 1;

  // xg prefetch (one step ahead)
  float xv0 = 0.f, xv1 = 0.f, xv2 = 0.f, xv3 = 0.f;
  if (tid < 128) {
    const float* xp = xg + ((size_t)0 * Gn + unit) * Bn + gb;
    xv0 = __ldcg(xp);
    xv1 = __ldcg(xp + (size_t)Hn * Bn);
    xv2 = __ldcg(xp + (size_t)2 * Hn * Bn);
    xv3 = __ldcg(xp + (size_t)3 * Hn * Bn);
  }

  for (int t = 0; t < Tn; t++) {
    // ---- stage z[b][j] = h_{t-1}; each warp gates on ITS producers' flags
    if (t == 0) {
      const float4* h4 = reinterpret_cast<const float4*>(
          h0 + (size_t)l * Bn * Hn + (size_t)grp * GB * Hn);
#pragma unroll
      for (int i = 0; i < 2; i++) {
        int e = tid + i * RTPB;            // 0..1023
        int b = e >> 7, jq = e & 127;
        float4 v = __ldcg(h4 + b * 128 + jq);
        zsh4[b * ZP4 + jq] = v;
      }
    } else {
      unsigned need = base + (unsigned)t;   // producer flag after step t-1
      unsigned f0, f1;
      do {
        asm volatile("ld.relaxed.gpu.global.b32 %0, [%1];"
                     : "=r"(f0) : "l"(gflags + p0) : "memory");
        asm volatile("ld.relaxed.gpu.global.b32 %0, [%1];"
                     : "=r"(f1) : "l"(gflags + p1) : "memory");
      } while (f0 < need || f1 < need);
      asm volatile("fence.acq_rel.gpu;" ::: "memory");
      int b = lane >> 2, q = lane & 3;
      const float4* hb = reinterpret_cast<const float4*>(
          hout + ((size_t)(t - 1) * Bn + grp * GB) * Hn);
      float4 v0 = __ldcg(hb + b * 128 + p0 * 4 + q);
      float4 v1 = __ldcg(hb + b * 128 + p1 * 4 + q);
      zsh4[b * ZP4 + p0 * 4 + q] = v0;
      zsh4[b * ZP4 + p1 * 4 + q] = v1;
    }
    __syncthreads();

    // ---- prefetch xg for NEXT step (in flight through GEMM+gates)
    float nx0 = 0.f, nx1 = 0.f, nx2 = 0.f, nx3 = 0.f;
    if (tid < 128 && t + 1 < Tn) {
      const float* xp = xg + ((size_t)(t + 1) * Gn + unit) * Bn + gb;
      nx0 = __ldcg(xp);
      nx1 = __ldcg(xp + (size_t)Hn * Bn);
      nx2 = __ldcg(xp + (size_t)2 * Hn * Bn);
      nx3 = __ldcg(xp + (size_t)3 * Hn * Bn);
    }

    // ---- GEMM: 8 accumulators/thread (4 rows x 2 batches), K-slice of 64
    {
      const float* w0 = Wsh + rg * WPITCH + ks * 64;
      const float* zp0 = zsh + bp * ZPITCH + ks * 64;
      const float* zp1 = zp0 + 4 * ZPITCH;
      float a00 = 0.f, a01 = 0.f, a10 = 0.f, a11 = 0.f;
      float a20 = 0.f, a21 = 0.f, a30 = 0.f, a31 = 0.f;
#pragma unroll 4
      for (int k = 0; k < 64; k += 4) {
        float4 za = *reinterpret_cast<const float4*>(zp0 + k);
        float4 zb = *reinterpret_cast<const float4*>(zp1 + k);
        float4 w0v = *reinterpret_cast<const float4*>(w0 + k);
        float4 w1v = *reinterpret_cast<const float4*>(w0 + 16 * WPITCH + k);
        float4 w2v = *reinterpret_cast<const float4*>(w0 + 32 * WPITCH + k);
        float4 w3v = *reinterpret_cast<const float4*>(w0 + 48 * WPITCH + k);
        a00 = fmaf(w0v.x, za.x, a00); a01 = fmaf(w0v.x, zb.x, a01);
        a10 = fmaf(w1v.x, za.x, a10); a11 = fmaf(w1v.x, zb.x, a11);
        a20 = fmaf(w2v.x, za.x, a20); a21 = fmaf(w2v.x, zb.x, a21);
        a30 = fmaf(w3v.x, za.x, a30); a31 = fmaf(w3v.x, zb.x, a31);
        a00 = fmaf(w0v.y, za.y, a00); a01 = fmaf(w0v.y, zb.y, a01);
        a10 = fmaf(w1v.y, za.y, a10); a11 = fmaf(w1v.y, zb.y, a11);
        a20 = fmaf(w2v.y, za.y, a20); a21 = fmaf(w2v.y, zb.y, a21);
        a30 = fmaf(w3v.y, za.y, a30); a31 = fmaf(w3v.y, zb.y, a31);
        a00 = fmaf(w0v.z, za.z, a00); a01 = fmaf(w0v.z, zb.z, a01);
        a10 = fmaf(w1v.z, za.z, a10); a11 = fmaf(w1v.z, zb.z, a11);
        a20 = fmaf(w2v.z, za.z, a20); a21 = fmaf(w2v.z, zb.z, a21);
        a30 = fmaf(w3v.z, za.z, a30); a31 = fmaf(w3v.z, zb.z, a31);
        a00 = fmaf(w0v.w, za.w, a00); a01 = fmaf(w0v.w, zb.w, a01);
        a10 = fmaf(w1v.w, za.w, a10); a11 = fmaf(w1v.w, zb.w, a11);
        a20 = fmaf(w2v.w, za.w, a20); a21 = fmaf(w2v.w, zb.w, a21);
        a30 = fmaf(w3v.w, za.w, a30); a31 = fmaf(w3v.w, zb.w, a31);
      }
      float* pb = pre + (ks * CROWS + rg) * GB + bp;
      pb[0 * 16 * GB + 0] = a00; pb[0 * 16 * GB + 4] = a01;
      pb[1 * 16 * GB + 0] = a10; pb[1 * 16 * GB + 4] = a11;
      pb[2 * 16 * GB + 0] = a20; pb[2 * 16 * GB + 4] = a21;
      pb[3 * 16 * GB + 0] = a30; pb[3 * 16 * GB + 4] = a31;
    }
    __syncthreads();

    // ---- gates + state (tid<128), then flag release
    if (tid < 128) {
      float g0 = xv0, g1 = xv1, g2 = xv2, g3 = xv3;
#pragma unroll
      for (int s = 0; s < KSn; s++) {
        g0 += pre[(s * CROWS + 0 * CUNITS + u) * GB + bl];
        g1 += pre[(s * CROWS + 1 * CUNITS + u) * GB + bl];
        g2 += pre[(s * CROWS + 2 * CUNITS + u) * GB + bl];
        g3 += pre[(s * CROWS + 3 * CUNITS + u) * GB + bl];
      }
      float gi = fsigm(g0);
      float gf = fsigm(g1);
      float gg = ftanh(g2);
      float go = fsigm(g3);
      c = gf * c + gi * gg;
      float h = go * ftanh(c);
      hout[((size_t)t * Bn + gb) * Hn + unit] = h;
      if (t == Tn - 1)
        out[(size_t)l * Bn * Hn + (size_t)gb * Hn + unit] = c;
      xv0 = nx0; xv1 = nx1; xv2 = nx2; xv3 = nx3;
    }
    __syncthreads();
    if (t < Tn - 1 && tid == 0) {
      asm volatile("fence.acq_rel.gpu;" ::: "memory");
      asm volatile("st.relaxed.gpu.global.b32 [%0], %1;"
                   :: "l"(g_flags + ct), "r"(base + (unsigned)t + 1u) : "memory");
    }
  }
}

extern "C" void kernel_launch(void* const* d_in, const int* in_sizes, int n_in,
                              void* d_out, int out_size) {
  const float* x    = (const float*)d_in[0];
  const float* h0   = (const float*)d_in[1];
  const float* c0   = (const float*)d_in[2];
  const float* w_ih = (const float*)d_in[3];
  const float* w_hh = (const float*)d_in[4];
  const float* b_ih = (const float*)d_in[5];
  const float* b_hh = (const float*)d_in[6];
  float* out = (float*)d_out;

  cudaFuncSetAttribute(xg_gemm_kernel,
                       cudaFuncAttributeMaxDynamicSharedMemorySize, GEMM_SMEM);
  cudaFuncSetAttribute(lstm_rec_kernel,
                       cudaFuncAttributeMaxDynamicSharedMemorySize, REC_SMEM);

  // pad launches so ncu -s 5 profiles a rec kernel
  init_kernel<<<1, 128>>>();
  init_kernel<<<1, 128>>>();
  for (int l = 0; l < Ln; l++) {
    xg_gemm_kernel<<<dim3(Tn / 4, Gn / TR), GT, GEMM_SMEM>>>(
        w_ih + (size_t)l * Gn * In, b_ih + (size_t)l * Gn, b_hh + (size_t)l * Gn,
        x, l ? 1 : 0, (l & 1) ^ 1);
    lstm_rec_kernel<<<NCTA, RTPB, REC_SMEM>>>(
        h0, c0, w_hh + (size_t)l * Gn * Hn, out, l, l & 1);
  }
}

// round 8
// speedup vs baseline: 1.1176x; 1.1176x over previous
#include <cuda_runtime.h>
#include <math.h>

#define Bn 32
#define Tn 2048
#define In 512
#define Hn 512
#define Ln 4
#define Gn 2048   // 4*H

// ---------------- phase A (layer-0 xg pre-GEMM) ----------------
#define GT 256
#define TR 128
#define TK 32
#define WPAD 132
#define ZPAD 132
#define GEMM_SMEM ((2*TK*WPAD + 2*TK*ZPAD) * 4)

// ---------------- wavefront kernel ----------------
#define WTPB 512
#define WPITCH 516
#define ZPITCH 516
#define XG_T 65536    // floats per (layer,t) block: 32cl * 64rows * 32b
#define WAVE_SMEM ((64*WPITCH + 32*ZPITCH + 2*64*32) * 4)

// Static scratch
__device__ float g_xg[(size_t)Ln * Tn * XG_T];        // [l][t][cl][64][32]  (~2.1GB)
__device__ float g_h[(size_t)Ln * Tn * Hn * Bn];      // [l][t][j][b]
__device__ unsigned g_flags[256];                     // [0:128) h-flags, [128:256) xg-flags

__global__ void init_kernel() {
  if (threadIdx.x < 256) g_flags[threadIdx.x] = 0u;
}

// packed fp32x2 FMA (Blackwell): acc += a*b elementwise on 2 lanes
#define FMA2(acc, a, b) \
  asm("fma.rn.f32x2 %0, %1, %2, %0;" : "+l"(acc) : "l"(a), "l"(b))

__device__ __forceinline__ float f2sum(unsigned long long v) {
  unsigned lo = (unsigned)v, hi = (unsigned)(v >> 32);
  return __uint_as_float(lo) + __uint_as_float(hi);
}

// ============ Phase A: xg[0][t][cl][64][32] = Wih0 @ x + bias ============
__global__ void __launch_bounds__(GT, 2) xg_gemm_kernel(
    const float* __restrict__ W,
    const float* __restrict__ bih, const float* __restrict__ bhh,
    const float* __restrict__ x)
{
  extern __shared__ float sm[];
  float* Ws = sm;                  // [2][TK][WPAD]
  float* Zs = sm + 2 * TK * WPAD;  // [2][TK][ZPAD]

  const int tid = threadIdx.x;
  const int t0 = blockIdx.x * 4;
  const int r0 = blockIdx.y * TR;
  const int trow = tid >> 4;
  const int tcol = tid & 15;

  float acc[8][8];
#pragma unroll
  for (int i = 0; i < 8; i++)
#pragma unroll
    for (int j = 0; j < 8; j++) acc[i][j] = 0.f;

  float4 wr[4], zr[4];

  auto ldg_chunk = [&](int kc) {
#pragma unroll
    for (int j = 0; j < 4; j++) {
      int idx = tid * 4 + j;
      int row = idx >> 3, kq = idx & 7;
      wr[j] = *reinterpret_cast<const float4*>(W + (size_t)(r0 + row) * In + kc + kq * 4);
    }
#pragma unroll
    for (int j = 0; j < 4; j++) {
      int idx = tid * 4 + j;
      int ki = idx & 7, tt = (idx >> 3) & 3, b = idx >> 5;
      zr[j] = *reinterpret_cast<const float4*>(x + ((size_t)b * Tn + t0 + tt) * In + kc + ki * 4);
    }
  };

  auto sts_chunk = [&](int buf) {
    float* Wb = Ws + buf * TK * WPAD;
    float* Zb = Zs + buf * TK * ZPAD;
#pragma unroll
    for (int j = 0; j < 4; j++) {
      int idx = tid * 4 + j;
      int row = idx >> 3, kq = idx & 7;
      Wb[(kq * 4 + 0) * WPAD + row] = wr[j].x;
      Wb[(kq * 4 + 1) * WPAD + row] = wr[j].y;
      Wb[(kq * 4 + 2) * WPAD + row] = wr[j].z;
      Wb[(kq * 4 + 3) * WPAD + row] = wr[j].w;
    }
#pragma unroll
    for (int j = 0; j < 4; j++) {
      int idx = tid * 4 + j;
      int ki = idx & 7, tt = (idx >> 3) & 3, b = idx >> 5;
      Zb[(ki * 4 + 0) * ZPAD + tt * 32 + b] = zr[j].x;
      Zb[(ki * 4 + 1) * ZPAD + tt * 32 + b] = zr[j].y;
      Zb[(ki * 4 + 2) * ZPAD + tt * 32 + b] = zr[j].z;
      Zb[(ki * 4 + 3) * ZPAD + tt * 32 + b] = zr[j].w;
    }
  };

  auto compute = [&](int buf) {
    const float* Wb = Ws + buf * TK * WPAD;
    const float* Zb = Zs + buf * TK * ZPAD;
#pragma unroll 8
    for (int kk = 0; kk < TK; kk++) {
      float4 wa = *reinterpret_cast<const float4*>(Wb + kk * WPAD + trow * 8);
      float4 wb2 = *reinterpret_cast<const float4*>(Wb + kk * WPAD + trow * 8 + 4);
      float4 za = *reinterpret_cast<const float4*>(Zb + kk * ZPAD + tcol * 8);
      float4 zb2 = *reinterpret_cast<const float4*>(Zb + kk * ZPAD + tcol * 8 + 4);
      float w8[8] = {wa.x, wa.y, wa.z, wa.w, wb2.x, wb2.y, wb2.z, wb2.w};
      float z8[8] = {za.x, za.y, za.z, za.w, zb2.x, zb2.y, zb2.z, zb2.w};
#pragma unroll
      for (int i = 0; i < 8; i++)
#pragma unroll
        for (int j = 0; j < 8; j++)
          acc[i][j] = fmaf(w8[i], z8[j], acc[i][j]);
    }
  };

  const int NCH = In / TK;   // 16
  ldg_chunk(0);
  sts_chunk(0);
  __syncthreads();
  ldg_chunk(TK);
  for (int c = 0; c < NCH; c++) {
    int buf = c & 1;
    if (c + 1 < NCH) sts_chunk(buf ^ 1);
    if (c + 2 < NCH) ldg_chunk((c + 2) * TK);
    compute(buf);
    __syncthreads();
  }

#pragma unroll
  for (int i = 0; i < 8; i++) {
    int row = r0 + trow * 8 + i;       // global gate row
    float bv = __ldg(bih + row) + __ldg(bhh + row);
    int tt = tcol >> 2;
    int b0 = (tcol & 3) * 8;
    int q = row >> 9, rem = row & 511;
    int clr = rem >> 4, ur = rem & 15;
    float* dst = g_xg + (size_t)(t0 + tt) * XG_T + clr * 2048 + (q * 16 + ur) * 32 + b0;
    float4 v0 = make_float4(acc[i][0] + bv, acc[i][1] + bv, acc[i][2] + bv, acc[i][3] + bv);
    float4 v1 = make_float4(acc[i][4] + bv, acc[i][5] + bv, acc[i][6] + bv, acc[i][7] + bv);
    *reinterpret_cast<float4*>(dst) = v0;
    *reinterpret_cast<float4*>(dst + 4) = v1;
  }
}

__device__ __forceinline__ float fsigm(float v) {
  return __fdividef(1.f, 1.f + __expf(-v));
}
__device__ __forceinline__ float ftanh(float v) {
  float e = __expf(-2.f * v);
  return __fdividef(1.f - e, 1.f + e);
}

// ============ Wavefront: 4 layer-teams x 32 CTAs, persistent ============
__global__ void __launch_bounds__(WTPB, 1) lstm_wave_kernel(
    const float* __restrict__ h0, const float* __restrict__ c0,
    const float* __restrict__ w_ih, const float* __restrict__ w_hh,
    const float* __restrict__ b_ih, const float* __restrict__ b_hh,
    float* __restrict__ out)
{
  extern __shared__ float smem[];
  float* Wsh = smem;                     // [64][WPITCH]
  float* zsh = Wsh + 64 * WPITCH;        // [32][ZPITCH]   z[b][j]
  float* pre = zsh + 32 * ZPITCH;        // [2][64][32]

  const int tid = threadIdx.x;
  const int ct = blockIdx.x;
  const int team = ct >> 5;              // layer
  const int cl = ct & 31;
  // rec GEMM mapping
  const int kh = tid >> 8;               // 0/1 K-half
  const int rg = (tid >> 4) & 15;        // rows rg, rg+16, rg+32, rg+48
  const int bg = tid & 15;               // batches bg, bg+16
  // gates / xg-production mapping
  const int u = tid >> 5;                // unit 0..15 (== warp id)
  const int bb = tid & 31;               // batch (== lane)
  const int unit = cl * 16 + u;

  // load Whh slice
  const float* Whh = w_hh + (size_t)team * Gn * Hn;
  for (int idx = tid; idx < 64 * 128; idx += WTPB) {
    int rr = idx >> 7, kk = idx & 127;
    int q = rr >> 4, uu = rr & 15;
    int grb = q * Hn + cl * 16 + uu;
    *reinterpret_cast<float4*>(Wsh + rr * WPITCH + kk * 4) =
        *reinterpret_cast<const float4*>(Whh + (size_t)grb * Hn + kk * 4);
  }
  float c = c0[(size_t)team * Bn * Hn + (size_t)bb * Hn + unit];

  // xg-production setup (teams 0..2 produce for team+1)
  const float* WihN = w_ih + (size_t)(team + 1) * Gn * In;
  int grow[4];
  float xbias[4];
  if (team < 3) {
#pragma unroll
    for (int i = 0; i < 4; i++) {
      grow[i] = i * Hn + cl * 16 + u;
      xbias[i] = __ldg(b_ih + (size_t)(team + 1) * Gn + grow[i]) +
                 __ldg(b_hh + (size_t)(team + 1) * Gn + grow[i]);
    }
  }

  unsigned* hfl = g_flags + team * 32;
  unsigned* xflp = g_flags + 128 + (team - 1) * 32 + cl;   // upstream xg flag (team>0)
  unsigned* my_hfl = g_flags + ct;
  unsigned* my_xfl = g_flags + 128 + ct;

  float xv0, xv1, xv2, xv3;

  for (int t = 0; t < Tn; t++) {
    // ---- wait: own-team h flags >= t; upstream xg flag >= t+1
    if (t > 0 || team > 0) {
      if (tid < 32) {
        bool ok;
        do {
          ok = true;
          if (t > 0) {
            unsigned v;
            asm volatile("ld.relaxed.gpu.global.b32 %0, [%1];"
                         : "=r"(v) : "l"(hfl + tid) : "memory");
            ok &= (v >= (unsigned)t);
          }
          if (team > 0) {
            unsigned v2;
            asm volatile("ld.relaxed.gpu.global.b32 %0, [%1];"
                         : "=r"(v2) : "l"(xflp) : "memory");
            ok &= (v2 >= (unsigned)(t + 1));
          }
        } while (!__all_sync(0xffffffffu, ok));
        asm volatile("fence.acq_rel.gpu;" ::: "memory");
      }
      __syncthreads();
    }

    // ---- stage z[b][j] = h_{t-1}, prefetch xg[t]
    if (t == 0) {
      const float4* h4 = reinterpret_cast<const float4*>(h0 + (size_t)team * Bn * Hn);
#pragma unroll
      for (int i = 0; i < 8; i++) {
        int idx = tid + i * WTPB;         // 4096 float4; [b][j] layout
        int b = idx >> 7, jq = idx & 127;
        float4 v = __ldcg(h4 + idx);
        *reinterpret_cast<float4*>(zsh + b * ZPITCH + jq * 4) = v;
      }
    } else {
      const float4* h4 = reinterpret_cast<const float4*>(
          g_h + ((size_t)team * Tn + (t - 1)) * Hn * Bn);   // [j][b]
#pragma unroll
      for (int i = 0; i < 8; i++) {
        int idx = tid + i * WTPB;
        int j = idx >> 3, b4 = (idx & 7) * 4;
        float4 v = __ldcg(h4 + idx);
        zsh[(b4 + 0) * ZPITCH + j] = v.x;
        zsh[(b4 + 1) * ZPITCH + j] = v.y;
        zsh[(b4 + 2) * ZPITCH + j] = v.z;
        zsh[(b4 + 3) * ZPITCH + j] = v.w;
      }
    }
    {
      const float* xp = g_xg + ((size_t)team * Tn + t) * XG_T + cl * 2048 + u * 32 + bb;
      xv0 = __ldcg(xp);
      xv1 = __ldcg(xp + 512);
      xv2 = __ldcg(xp + 1024);
      xv3 = __ldcg(xp + 1536);
    }
    __syncthreads();

    // ---- rec GEMM (f32x2 packed): 4 rows x 2 batches x 256 K per thread
    {
      const float* wr = Wsh + rg * WPITCH + kh * 256;
      const float* zp = zsh + bg * ZPITCH + kh * 256;
      unsigned long long acc[4][2];
#pragma unroll
      for (int i = 0; i < 4; i++) { acc[i][0] = 0ull; acc[i][1] = 0ull; }
#pragma unroll 4
      for (int k = 0; k < 256; k += 4) {
        ulonglong2 z0 = *reinterpret_cast<const ulonglong2*>(zp + k);
        ulonglong2 z1 = *reinterpret_cast<const ulonglong2*>(zp + 16 * ZPITCH + k);
#pragma unroll
        for (int i = 0; i < 4; i++) {
          ulonglong2 w = *reinterpret_cast<const ulonglong2*>(wr + i * 16 * WPITCH + k);
          FMA2(acc[i][0], w.x, z0.x); FMA2(acc[i][0], w.y, z0.y);
          FMA2(acc[i][1], w.x, z1.x); FMA2(acc[i][1], w.y, z1.y);
        }
      }
#pragma unroll
      for (int i = 0; i < 4; i++) {
        pre[(kh * 64 + rg + 16 * i) * 32 + bg] = f2sum(acc[i][0]);
        pre[(kh * 64 + rg + 16 * i) * 32 + bg + 16] = f2sum(acc[i][1]);
      }
    }
    __syncthreads();

    // ---- gates + state (all 512 threads: one (u, b) each)
    {
      float g0 = xv0 + pre[(0 * 16 + u) * 32 + bb] + pre[(64 + 0 * 16 + u) * 32 + bb];
      float g1 = xv1 + pre[(1 * 16 + u) * 32 + bb] + pre[(64 + 1 * 16 + u) * 32 + bb];
      float g2 = xv2 + pre[(2 * 16 + u) * 32 + bb] + pre[(64 + 2 * 16 + u) * 32 + bb];
      float g3 = xv3 + pre[(3 * 16 + u) * 32 + bb] + pre[(64 + 3 * 16 + u) * 32 + bb];
      float gi = fsigm(g0);
      float gf = fsigm(g1);
      float gg = ftanh(g2);
      float go = fsigm(g3);
      c = gf * c + gi * gg;
      float h = go * ftanh(c);
      __stcg(g_h + ((size_t)team * Tn + t) * Hn * Bn + (size_t)unit * 32 + bb, h);
      if (t == Tn - 1)
        out[(size_t)team * Bn * Hn + (size_t)bb * Hn + unit] = c;
    }
    __syncthreads();
    if (tid == 0) {
      asm volatile("fence.acq_rel.gpu;" ::: "memory");
      asm volatile("st.relaxed.gpu.global.b32 [%0], %1;"
                   :: "l"(my_hfl), "r"((unsigned)(t + 1)) : "memory");
    }

    // ---- xg production for layer team+1, index t-1 (uses current z = h_{t-1})
    if (team < 3 && t >= 1) {
      unsigned long long xa[4];
#pragma unroll
      for (int i = 0; i < 4; i++)
        xa[i] = (unsigned long long)__float_as_uint(xbias[i]);
      const float* zrow = zsh + bb * ZPITCH;
#pragma unroll 4
      for (int k = 0; k < 512; k += 4) {
        ulonglong2 z = *reinterpret_cast<const ulonglong2*>(zrow + k);
#pragma unroll
        for (int i = 0; i < 4; i++) {
          ulonglong2 w = __ldg(reinterpret_cast<const ulonglong2*>(
              WihN + (size_t)grow[i] * In + k));
          FMA2(xa[i], w.x, z.x); FMA2(xa[i], w.y, z.y);
        }
      }
      size_t xbase = ((size_t)(team + 1) * Tn + (t - 1)) * XG_T + cl * 2048 + u * 32 + bb;
#pragma unroll
      for (int i = 0; i < 4; i++)
        __stcg(g_xg + xbase + i * 512, f2sum(xa[i]));
    }
    __syncthreads();
    if (team < 3 && t >= 1 && tid == 0) {
      asm volatile("fence.acq_rel.gpu;" ::: "memory");
      asm volatile("st.relaxed.gpu.global.b32 [%0], %1;"
                   :: "l"(my_xfl), "r"((unsigned)t) : "memory");
    }
  }

  // ---- epilogue: produce xg[team+1][2047] from h_2047
  if (team < 3) {
    if (tid < 32) {
      bool ok;
      do {
        unsigned v;
        asm volatile("ld.relaxed.gpu.global.b32 %0, [%1];"
                     : "=r"(v) : "l"(hfl + tid) : "memory");
        ok = (v >= (unsigned)Tn);
      } while (!__all_sync(0xffffffffu, ok));
      asm volatile("fence.acq_rel.gpu;" ::: "memory");
    }
    __syncthreads();
    {
      const float4* h4 = reinterpret_cast<const float4*>(
          g_h + ((size_t)team * Tn + (Tn - 1)) * Hn * Bn);
#pragma unroll
      for (int i = 0; i < 8; i++) {
        int idx = tid + i * WTPB;
        int j = idx >> 3, b4 = (idx & 7) * 4;
        float4 v = __ldcg(h4 + idx);
        zsh[(b4 + 0) * ZPITCH + j] = v.x;
        zsh[(b4 + 1) * ZPITCH + j] = v.y;
        zsh[(b4 + 2) * ZPITCH + j] = v.z;
        zsh[(b4 + 3) * ZPITCH + j] = v.w;
      }
    }
    __syncthreads();
    {
      unsigned long long xa[4];
#pragma unroll
      for (int i = 0; i < 4; i++)
        xa[i] = (unsigned long long)__float_as_uint(xbias[i]);
      const float* zrow = zsh + bb * ZPITCH;
#pragma unroll 4
      for (int k = 0; k < 512; k += 4) {
        ulonglong2 z = *reinterpret_cast<const ulonglong2*>(zrow + k);
#pragma unroll
        for (int i = 0; i < 4; i++) {
          ulonglong2 w = __ldg(reinterpret_cast<const ulonglong2*>(
              WihN + (size_t)grow[i] * In + k));
          FMA2(xa[i], w.x, z.x); FMA2(xa[i], w.y, z.y);
        }
      }
      size_t xbase = ((size_t)(team + 1) * Tn + (Tn - 1)) * XG_T + cl * 2048 + u * 32 + bb;
#pragma unroll
      for (int i = 0; i < 4; i++)
        __stcg(g_xg + xbase + i * 512, f2sum(xa[i]));
    }
    __syncthreads();
    if (tid == 0) {
      asm volatile("fence.acq_rel.gpu;" ::: "memory");
      asm volatile("st.relaxed.gpu.global.b32 [%0], %1;"
                   :: "l"(my_xfl), "r"((unsigned)Tn) : "memory");
    }
  }
}

extern "C" void kernel_launch(void* const* d_in, const int* in_sizes, int n_in,
                              void* d_out, int out_size) {
  const float* x    = (const float*)d_in[0];
  const float* h0   = (const float*)d_in[1];
  const float* c0   = (const float*)d_in[2];
  const float* w_ih = (const float*)d_in[3];
  const float* w_hh = (const float*)d_in[4];
  const float* b_ih = (const float*)d_in[5];
  const float* b_hh = (const float*)d_in[6];
  float* out = (float*)d_out;

  cudaFuncSetAttribute(xg_gemm_kernel,
                       cudaFuncAttributeMaxDynamicSharedMemorySize, GEMM_SMEM);
  cudaFuncSetAttribute(lstm_wave_kernel,
                       cudaFuncAttributeMaxDynamicSharedMemorySize, WAVE_SMEM);

  // 3 launches/call: ncu -s 5 lands on lstm_wave_kernel of the 2nd call
  init_kernel<<<1, 256>>>();
  xg_gemm_kernel<<<dim3(Tn / 4, Gn / TR), GT, GEMM_SMEM>>>(
      w_ih, b_ih, b_hh, x);
  lstm_wave_kernel<<<128, WTPB, WAVE_SMEM>>>(h0, c0, w_ih, w_hh, b_ih, b_hh, out);
}

// round 9
// speedup vs baseline: 1.6222x; 1.4515x over previous
#include <cuda_runtime.h>
#include <math.h>

#define Bn 32
#define Tn 2048
#define In 512
#define Hn 512
#define Ln 4
#define Gn 2048   // 4*H

// ---------------- phase A (layer-0 xg pre-GEMM) ----------------
#define GT 256
#define TR 128
#define TK 32
#define WPAD 132
#define ZPAD 132
#define GEMM_SMEM ((2*TK*WPAD + 2*TK*ZPAD) * 4)

// ---------------- wavefront kernel ----------------
#define WTPB 512
#define WHP 512       // Whh smem pitch (broadcast loads -> no conflicts)
#define ZPITCH 516
#define XG_T 65536    // floats per (layer,t) block: 32cl * 64rows * 32b
// smem: Whh 64*512 | z 32*516 | pre 2*64*32 | wbuf 2*4*512
#define SM_WHH 0
#define SM_Z   (64*WHP)
#define SM_PRE (SM_Z + 32*ZPITCH)
#define SM_WBUF (SM_PRE + 2*64*32)
#define WAVE_SMEM ((SM_WBUF + 2*4*512) * 4)

// Static scratch
__device__ float g_xg[(size_t)Ln * Tn * XG_T];        // [l][t][cl][64][32]
__device__ float g_h[(size_t)Ln * Tn * Hn * Bn];      // [l][t][j][b]
__device__ unsigned g_flags[256];                     // [0:128) h, [128:256) xg

__global__ void init_kernel() {
  if (threadIdx.x < 256) g_flags[threadIdx.x] = 0u;
}

#define FMA2(acc, a, b) \
  asm("fma.rn.f32x2 %0, %1, %2, %0;" : "+l"(acc) : "l"(a), "l"(b))

__device__ __forceinline__ float f2sum(unsigned long long v) {
  unsigned lo = (unsigned)v, hi = (unsigned)(v >> 32);
  return __uint_as_float(lo) + __uint_as_float(hi);
}

__device__ __forceinline__ unsigned smem_u32(const void* p) {
  return (unsigned)__cvta_generic_to_shared(p);
}

// ============ Phase A: xg[0][t][cl][64][32] = Wih0 @ x + bias ============
__global__ void __launch_bounds__(GT, 2) xg_gemm_kernel(
    const float* __restrict__ W,
    const float* __restrict__ bih, const float* __restrict__ bhh,
    const float* __restrict__ x)
{
  extern __shared__ float sm[];
  float* Ws = sm;
  float* Zs = sm + 2 * TK * WPAD;

  const int tid = threadIdx.x;
  const int t0 = blockIdx.x * 4;
  const int r0 = blockIdx.y * TR;
  const int trow = tid >> 4;
  const int tcol = tid & 15;

  float acc[8][8];
#pragma unroll
  for (int i = 0; i < 8; i++)
#pragma unroll
    for (int j = 0; j < 8; j++) acc[i][j] = 0.f;

  float4 wr[4], zr[4];

  auto ldg_chunk = [&](int kc) {
#pragma unroll
    for (int j = 0; j < 4; j++) {
      int idx = tid * 4 + j;
      int row = idx >> 3, kq = idx & 7;
      wr[j] = *reinterpret_cast<const float4*>(W + (size_t)(r0 + row) * In + kc + kq * 4);
    }
#pragma unroll
    for (int j = 0; j < 4; j++) {
      int idx = tid * 4 + j;
      int ki = idx & 7, tt = (idx >> 3) & 3, b = idx >> 5;
      zr[j] = *reinterpret_cast<const float4*>(x + ((size_t)b * Tn + t0 + tt) * In + kc + ki * 4);
    }
  };

  auto sts_chunk = [&](int buf) {
    float* Wb = Ws + buf * TK * WPAD;
    float* Zb = Zs + buf * TK * ZPAD;
#pragma unroll
    for (int j = 0; j < 4; j++) {
      int idx = tid * 4 + j;
      int row = idx >> 3, kq = idx & 7;
      Wb[(kq * 4 + 0) * WPAD + row] = wr[j].x;
      Wb[(kq * 4 + 1) * WPAD + row] = wr[j].y;
      Wb[(kq * 4 + 2) * WPAD + row] = wr[j].z;
      Wb[(kq * 4 + 3) * WPAD + row] = wr[j].w;
    }
#pragma unroll
    for (int j = 0; j < 4; j++) {
      int idx = tid * 4 + j;
      int ki = idx & 7, tt = (idx >> 3) & 3, b = idx >> 5;
      Zb[(ki * 4 + 0) * ZPAD + tt * 32 + b] = zr[j].x;
      Zb[(ki * 4 + 1) * ZPAD + tt * 32 + b] = zr[j].y;
      Zb[(ki * 4 + 2) * ZPAD + tt * 32 + b] = zr[j].z;
      Zb[(ki * 4 + 3) * ZPAD + tt * 32 + b] = zr[j].w;
    }
  };

  auto compute = [&](int buf) {
    const float* Wb = Ws + buf * TK * WPAD;
    const float* Zb = Zs + buf * TK * ZPAD;
#pragma unroll 8
    for (int kk = 0; kk < TK; kk++) {
      float4 wa = *reinterpret_cast<const float4*>(Wb + kk * WPAD + trow * 8);
      float4 wb2 = *reinterpret_cast<const float4*>(Wb + kk * WPAD + trow * 8 + 4);
      float4 za = *reinterpret_cast<const float4*>(Zb + kk * ZPAD + tcol * 8);
      float4 zb2 = *reinterpret_cast<const float4*>(Zb + kk * ZPAD + tcol * 8 + 4);
      float w8[8] = {wa.x, wa.y, wa.z, wa.w, wb2.x, wb2.y, wb2.z, wb2.w};
      float z8[8] = {za.x, za.y, za.z, za.w, zb2.x, zb2.y, zb2.z, zb2.w};
#pragma unroll
      for (int i = 0; i < 8; i++)
#pragma unroll
        for (int j = 0; j < 8; j++)
          acc[i][j] = fmaf(w8[i], z8[j], acc[i][j]);
    }
  };

  const int NCH = In / TK;
  ldg_chunk(0);
  sts_chunk(0);
  __syncthreads();
  ldg_chunk(TK);
  for (int c = 0; c < NCH; c++) {
    int buf = c & 1;
    if (c + 1 < NCH) sts_chunk(buf ^ 1);
    if (c + 2 < NCH) ldg_chunk((c + 2) * TK);
    compute(buf);
    __syncthreads();
  }

#pragma unroll
  for (int i = 0; i < 8; i++) {
    int row = r0 + trow * 8 + i;
    float bv = __ldg(bih + row) + __ldg(bhh + row);
    int tt = tcol >> 2;
    int b0 = (tcol & 3) * 8;
    int q = row >> 9, rem = row & 511;
    int clr = rem >> 4, ur = rem & 15;
    float* dst = g_xg + (size_t)(t0 + tt) * XG_T + clr * 2048 + (q * 16 + ur) * 32 + b0;
    float4 v0 = make_float4(acc[i][0] + bv, acc[i][1] + bv, acc[i][2] + bv, acc[i][3] + bv);
    float4 v1 = make_float4(acc[i][4] + bv, acc[i][5] + bv, acc[i][6] + bv, acc[i][7] + bv);
    *reinterpret_cast<float4*>(dst) = v0;
    *reinterpret_cast<float4*>(dst + 4) = v1;
  }
}

__device__ __forceinline__ float fsigm(float v) {
  return __fdividef(1.f, 1.f + __expf(-v));
}
__device__ __forceinline__ float ftanh(float v) {
  float e = __expf(-2.f * v);
  return __fdividef(1.f - e, 1.f + e);
}

// ============ Wavefront: 4 layer-teams x 32 CTAs, persistent ============
__global__ void __launch_bounds__(WTPB, 1) lstm_wave_kernel(
    const float* __restrict__ h0, const float* __restrict__ c0,
    const float* __restrict__ w_ih, const float* __restrict__ w_hh,
    const float* __restrict__ b_ih, const float* __restrict__ b_hh,
    float* __restrict__ out)
{
  extern __shared__ float smem[];
  float* Wsh = smem + SM_WHH;            // [64][512]
  float* zsh = smem + SM_Z;              // [32][516]  z[b][j]
  float* pre = smem + SM_PRE;            // [2][64][32]; reused as xps[8][4][32]
  float* wbuf = smem + SM_WBUF;          // [2][4][512] Wih chunk ring
  const unsigned wbuf_u32 = smem_u32(wbuf);

  const int tid = threadIdx.x;
  const int ct = blockIdx.x;
  const int team = ct >> 5;              // layer
  const int cl = ct & 31;
  // rec GEMM mapping
  const int kh = tid >> 8;               // K-half
  const int rg = (tid >> 4) & 15;        // rows rg, +16, +32, +48
  const int bg = tid & 15;               // batches bg, bg+16
  // gates mapping
  const int u = tid >> 5;                // unit 0..15 (warp id)
  const int bb = tid & 31;               // batch (lane)
  const int unit = cl * 16 + u;
  // xg-phase mapping
  const int xkq = tid >> 6;              // 0..7  (64-wide K slice)
  const int xrr = (tid >> 4) & 3;        // row in chunk
  const int xbq = tid & 15;              // batches xbq, xbq+16

  // load Whh slice
  const float* Whh = w_hh + (size_t)team * Gn * Hn;
  for (int idx = tid; idx < 64 * 128; idx += WTPB) {
    int rr = idx >> 7, kk = idx & 127;
    int q = rr >> 4, uu = rr & 15;
    int grb = q * Hn + cl * 16 + uu;
    *reinterpret_cast<float4*>(Wsh + rr * WHP + kk * 4) =
        *reinterpret_cast<const float4*>(Whh + (size_t)grb * Hn + kk * 4);
  }
  float c = c0[(size_t)team * Bn * Hn + (size_t)bb * Hn + unit];

  const float* WihN = w_ih + (size_t)(team + 1) * Gn * In;
  const float* bihN = b_ih + (size_t)(team + 1) * Gn;
  const float* bhhN = b_hh + (size_t)(team + 1) * Gn;

  unsigned* hfl = g_flags + team * 32;
  unsigned* xflp = g_flags + 128 + (team - 1) * 32 + cl;
  unsigned* my_hfl = g_flags + ct;
  unsigned* my_xfl = g_flags + 128 + ct;

  // issue one 8KB chunk (4 consecutive Wih rows) into ring slot cidx&1
  auto issue_chunk = [&](int cidx) {
    int grow0 = (cidx >> 2) * Hn + cl * 16 + (cidx & 3) * 4;
    const char* src = reinterpret_cast<const char*>(WihN + (size_t)grow0 * In) + tid * 16;
    unsigned dst = wbuf_u32 + (unsigned)((cidx & 1) * 8192 + tid * 16);
    asm volatile("cp.async.cg.shared.global [%0], [%1], 16;" :: "r"(dst), "l"(src));
    asm volatile("cp.async.commit_group;" ::: "memory");
  };

  // run 16 xg phases producing xg[team+1][tt] from current z
  auto xg_phases = [&](int tt) {
    float* xps = pre;   // [8][4][32]
    size_t xbase = ((size_t)(team + 1) * Tn + tt) * XG_T + cl * 2048;
#pragma unroll 1
    for (int p = 0; p < 16; p++) {
      if (p == 15) asm volatile("cp.async.wait_group 0;" ::: "memory");
      else         asm volatile("cp.async.wait_group 1;" ::: "memory");
      __syncthreads();
      {
        const float* wrow = wbuf + (p & 1) * 2048 + xrr * 512 + xkq * 64;
        const float* zp0 = zsh + xbq * ZPITCH + xkq * 64;
        const float* zp1 = zp0 + 16 * ZPITCH;
        unsigned long long a0 = 0ull, a1 = 0ull;
#pragma unroll 4
        for (int k = 0; k < 64; k += 4) {
          ulonglong2 w = *reinterpret_cast<const ulonglong2*>(wrow + k);
          ulonglong2 z0 = *reinterpret_cast<const ulonglong2*>(zp0 + k);
          ulonglong2 z1 = *reinterpret_cast<const ulonglong2*>(zp1 + k);
          FMA2(a0, w.x, z0.x); FMA2(a0, w.y, z0.y);
          FMA2(a1, w.x, z1.x); FMA2(a1, w.y, z1.y);
        }
        xps[(xkq * 4 + xrr) * 32 + xbq] = f2sum(a0);
        xps[(xkq * 4 + xrr) * 32 + xbq + 16] = f2sum(a1);
      }
      __syncthreads();
      if (tid < 128) {
        int rr2 = tid >> 5, bb2 = tid & 31;
        int grow = (p >> 2) * Hn + cl * 16 + (p & 3) * 4 + rr2;
        float s = __ldg(bihN + grow) + __ldg(bhhN + grow);
#pragma unroll
        for (int q2 = 0; q2 < 8; q2++)
          s += xps[(q2 * 4 + rr2) * 32 + bb2];
        __stcg(g_xg + xbase + (4 * p + rr2) * 32 + bb2, s);
      }
      if (p + 2 < 16) issue_chunk(p + 2);
    }
  };

  float xv0, xv1, xv2, xv3;

  for (int t = 0; t < Tn; t++) {
    // ---- wait: own-team h flags >= t; upstream xg flag >= t+1
    if (t > 0 || team > 0) {
      if (tid < 32) {
        bool ok;
        do {
          ok = true;
          if (t > 0) {
            unsigned v;
            asm volatile("ld.relaxed.gpu.global.b32 %0, [%1];"
                         : "=r"(v) : "l"(hfl + tid) : "memory");
            ok &= (v >= (unsigned)t);
          }
          if (team > 0) {
            unsigned v2;
            asm volatile("ld.relaxed.gpu.global.b32 %0, [%1];"
                         : "=r"(v2) : "l"(xflp) : "memory");
            ok &= (v2 >= (unsigned)(t + 1));
          }
        } while (!__all_sync(0xffffffffu, ok));
        asm volatile("fence.acq_rel.gpu;" ::: "memory");
      }
      __syncthreads();
    }

    // ---- prologue: prefetch first two Wih chunks (hidden under stage+rec)
    if (team < 3 && t >= 1) {
      issue_chunk(0);
      issue_chunk(1);
    }

    // ---- stage z[b][j] = h_{t-1}, prefetch xg[t]
    if (t == 0) {
      const float4* h4 = reinterpret_cast<const float4*>(h0 + (size_t)team * Bn * Hn);
#pragma unroll
      for (int i = 0; i < 2; i++) {
        int idx = tid + i * WTPB;
        int b = idx >> 7, jq = idx & 127;
        float4 v = __ldcg(h4 + idx);
        *reinterpret_cast<float4*>(zsh + b * ZPITCH + jq * 4) = v;
      }
    } else {
      const float4* h4 = reinterpret_cast<const float4*>(
          g_h + ((size_t)team * Tn + (t - 1)) * Hn * Bn);   // [j][b]
#pragma unroll
      for (int i = 0; i < 8; i++) {
        int idx = tid + i * WTPB;
        int j = idx >> 3, b4 = (idx & 7) * 4;
        float4 v = __ldcg(h4 + idx);
        zsh[(b4 + 0) * ZPITCH + j] = v.x;
        zsh[(b4 + 1) * ZPITCH + j] = v.y;
        zsh[(b4 + 2) * ZPITCH + j] = v.z;
        zsh[(b4 + 3) * ZPITCH + j] = v.w;
      }
    }
    {
      const float* xp = g_xg + ((size_t)team * Tn + t) * XG_T + cl * 2048 + u * 32 + bb;
      xv0 = __ldcg(xp);
      xv1 = __ldcg(xp + 512);
      xv2 = __ldcg(xp + 1024);
      xv3 = __ldcg(xp + 1536);
    }
    __syncthreads();

    // ---- rec GEMM (f32x2): 4 rows x 2 batches x 256 K per thread
    {
      const float* wr = Wsh + rg * WHP + kh * 256;
      const float* zp = zsh + bg * ZPITCH + kh * 256;
      unsigned long long acc[4][2];
#pragma unroll
      for (int i = 0; i < 4; i++) { acc[i][0] = 0ull; acc[i][1] = 0ull; }
#pragma unroll 4
      for (int k = 0; k < 256; k += 4) {
        ulonglong2 z0 = *reinterpret_cast<const ulonglong2*>(zp + k);
        ulonglong2 z1 = *reinterpret_cast<const ulonglong2*>(zp + 16 * ZPITCH + k);
#pragma unroll
        for (int i = 0; i < 4; i++) {
          ulonglong2 w = *reinterpret_cast<const ulonglong2*>(wr + i * 16 * WHP + k);
          FMA2(acc[i][0], w.x, z0.x); FMA2(acc[i][0], w.y, z0.y);
          FMA2(acc[i][1], w.x, z1.x); FMA2(acc[i][1], w.y, z1.y);
        }
      }
#pragma unroll
      for (int i = 0; i < 4; i++) {
        pre[(kh * 64 + rg + 16 * i) * 32 + bg] = f2sum(acc[i][0]);
        pre[(kh * 64 + rg + 16 * i) * 32 + bg + 16] = f2sum(acc[i][1]);
      }
    }
    __syncthreads();

    // ---- gates + state
    {
      float g0 = xv0 + pre[(0 * 16 + u) * 32 + bb] + pre[(64 + 0 * 16 + u) * 32 + bb];
      float g1 = xv1 + pre[(1 * 16 + u) * 32 + bb] + pre[(64 + 1 * 16 + u) * 32 + bb];
      float g2 = xv2 + pre[(2 * 16 + u) * 32 + bb] + pre[(64 + 2 * 16 + u) * 32 + bb];
      float g3 = xv3 + pre[(3 * 16 + u) * 32 + bb] + pre[(64 + 3 * 16 + u) * 32 + bb];
      float gi = fsigm(g0);
      float gf = fsigm(g1);
      float gg = ftanh(g2);
      float go = fsigm(g3);
      c = gf * c + gi * gg;
      float h = go * ftanh(c);
      __stcg(g_h + ((size_t)team * Tn + t) * Hn * Bn + (size_t)unit * 32 + bb, h);
      if (t == Tn - 1)
        out[(size_t)team * Bn * Hn + (size_t)bb * Hn + unit] = c;
    }
    __syncthreads();
    if (tid == 0) {
      asm volatile("fence.acq_rel.gpu;" ::: "memory");
      asm volatile("st.relaxed.gpu.global.b32 [%0], %1;"
                   :: "l"(my_hfl), "r"((unsigned)(t + 1)) : "memory");
    }

    // ---- xg production for layer team+1, t-1 (uses current z = h_{t-1})
    if (team < 3 && t >= 1) {
      xg_phases(t - 1);
      __syncthreads();
      if (tid == 0) {
        asm volatile("fence.acq_rel.gpu;" ::: "memory");
        asm volatile("st.relaxed.gpu.global.b32 [%0], %1;"
                     :: "l"(my_xfl), "r"((unsigned)t) : "memory");
      }
    }
  }

  // ---- epilogue: produce xg[team+1][2047] from h_2047
  if (team < 3) {
    if (tid < 32) {
      bool ok;
      do {
        unsigned v;
        asm volatile("ld.relaxed.gpu.global.b32 %0, [%1];"
                     : "=r"(v) : "l"(hfl + tid) : "memory");
        ok = (v >= (unsigned)Tn);
      } while (!__all_sync(0xffffffffu, ok));
      asm volatile("fence.acq_rel.gpu;" ::: "memory");
    }
    __syncthreads();
    issue_chunk(0);
    issue_chunk(1);
    {
      const float4* h4 = reinterpret_cast<const float4*>(
          g_h + ((size_t)team * Tn + (Tn - 1)) * Hn * Bn);
#pragma unroll
      for (int i = 0; i < 8; i++) {
        int idx = tid + i * WTPB;
        int j = idx >> 3, b4 = (idx & 7) * 4;
        float4 v = __ldcg(h4 + idx);
        zsh[(b4 + 0) * ZPITCH + j] = v.x;
        zsh[(b4 + 1) * ZPITCH + j] = v.y;
        zsh[(b4 + 2) * ZPITCH + j] = v.z;
        zsh[(b4 + 3) * ZPITCH + j] = v.w;
      }
    }
    __syncthreads();
    xg_phases(Tn - 1);
    __syncthreads();
    if (tid == 0) {
      asm volatile("fence.acq_rel.gpu;" ::: "memory");
      asm volatile("st.relaxed.gpu.global.b32 [%0], %1;"
                   :: "l"(my_xfl), "r"((unsigned)Tn) : "memory");
    }
  }
}

extern "C" void kernel_launch(void* const* d_in, const int* in_sizes, int n_in,
                              void* d_out, int out_size) {
  const float* x    = (const float*)d_in[0];
  const float* h0   = (const float*)d_in[1];
  const float* c0   = (const float*)d_in[2];
  const float* w_ih = (const float*)d_in[3];
  const float* w_hh = (const float*)d_in[4];
  const float* b_ih = (const float*)d_in[5];
  const float* b_hh = (const float*)d_in[6];
  float* out = (float*)d_out;

  cudaFuncSetAttribute(xg_gemm_kernel,
                       cudaFuncAttributeMaxDynamicSharedMemorySize, GEMM_SMEM);
  cudaFuncSetAttribute(lstm_wave_kernel,
                       cudaFuncAttributeMaxDynamicSharedMemorySize, WAVE_SMEM);

  // 6 launches: indices 0..5 -> ncu -s 5 lands on lstm_wave_kernel
  init_kernel<<<1, 256>>>();
  init_kernel<<<1, 256>>>();
  init_kernel<<<1, 256>>>();
  init_kernel<<<1, 256>>>();
  xg_gemm_kernel<<<dim3(Tn / 4, Gn / TR), GT, GEMM_SMEM>>>(w_ih, b_ih, b_hh, x);
  lstm_wave_kernel<<<128, WTPB, WAVE_SMEM>>>(h0, c0, w_ih, w_hh, b_ih, b_hh, out);
}

// round 11
// speedup vs baseline: 2.2300x; 1.3747x over previous
#include <cuda_runtime.h>
#include <math.h>

#define Bn 32
#define Tn 2048
#define In 512
#define Hn 512
#define Ln 4
#define Gn 2048   // 4*H

// ---------------- phase A (layer-0 xg pre-GEMM) ----------------
#define GT 256
#define TR 128
#define TK 32
#define WPAD 132
#define ZPAD 132
#define GEMM_SMEM ((2*TK*WPAD + 2*TK*ZPAD) * 4)

// ---------------- wavefront kernel ----------------
#define WTPB 512
#define WHP 512       // Whh smem pitch (broadcast loads -> no conflicts)
#define ZPITCH 516
#define XG_T 65536    // floats per (layer,t) block: 32cl * 64rows * 32b
// smem floats: Whh 64*512 | z 32*516 | pre 2*64*32 | wbuf 2*2048 | bsh 64
#define SM_WHH 0
#define SM_Z   (64*WHP)
#define SM_PRE (SM_Z + 32*ZPITCH)
#define SM_WBUF (SM_PRE + 2*64*32)
#define SM_BSH (SM_WBUF + 2*2048)
#define WAVE_SMEM ((SM_BSH + 64) * 4)

// Static scratch
__device__ float g_xg[(size_t)Ln * Tn * XG_T];        // [l][t][cl][64][32]
__device__ float g_h[(size_t)Ln * Tn * Hn * Bn];      // [l][t][j][b]
__device__ unsigned g_flags[256];                     // [0:128) h, [128:256) xg

__global__ void init_kernel() {
  if (threadIdx.x < 256) g_flags[threadIdx.x] = 0u;
}

#define FMA2(acc, a, b) \
  asm("fma.rn.f32x2 %0, %1, %2, %0;" : "+l"(acc) : "l"(a), "l"(b))

__device__ __forceinline__ float f2sum(unsigned long long v) {
  unsigned lo = (unsigned)v, hi = (unsigned)(v >> 32);
  return __uint_as_float(lo) + __uint_as_float(hi);
}

__device__ __forceinline__ unsigned smem_u32(const void* p) {
  return (unsigned)__cvta_generic_to_shared(p);
}

// ============ Phase A: xg[0][t][cl][64][32] = Wih0 @ x + bias ============
__global__ void __launch_bounds__(GT, 2) xg_gemm_kernel(
    const float* __restrict__ W,
    const float* __restrict__ bih, const float* __restrict__ bhh,
    const float* __restrict__ x)
{
  extern __shared__ float sm[];
  float* Ws = sm;
  float* Zs = sm + 2 * TK * WPAD;

  const int tid = threadIdx.x;
  const int t0 = blockIdx.x * 4;
  const int r0 = blockIdx.y * TR;
  const int trow = tid >> 4;
  const int tcol = tid & 15;

  float acc[8][8];
#pragma unroll
  for (int i = 0; i < 8; i++)
#pragma unroll
    for (int j = 0; j < 8; j++) acc[i][j] = 0.f;

  float4 wr[4], zr[4];

  auto ldg_chunk = [&](int kc) {
#pragma unroll
    for (int j = 0; j < 4; j++) {
      int idx = tid * 4 + j;
      int row = idx >> 3, kq = idx & 7;
      wr[j] = *reinterpret_cast<const float4*>(W + (size_t)(r0 + row) * In + kc + kq * 4);
    }
#pragma unroll
    for (int j = 0; j < 4; j++) {
      int idx = tid * 4 + j;
      int ki = idx & 7, tt = (idx >> 3) & 3, b = idx >> 5;
      zr[j] = *reinterpret_cast<const float4*>(x + ((size_t)b * Tn + t0 + tt) * In + kc + ki * 4);
    }
  };

  auto sts_chunk = [&](int buf) {
    float* Wb = Ws + buf * TK * WPAD;
    float* Zb = Zs + buf * TK * ZPAD;
#pragma unroll
    for (int j = 0; j < 4; j++) {
      int idx = tid * 4 + j;
      int row = idx >> 3, kq = idx & 7;
      Wb[(kq * 4 + 0) * WPAD + row] = wr[j].x;
      Wb[(kq * 4 + 1) * WPAD + row] = wr[j].y;
      Wb[(kq * 4 + 2) * WPAD + row] = wr[j].z;
      Wb[(kq * 4 + 3) * WPAD + row] = wr[j].w;
    }
#pragma unroll
    for (int j = 0; j < 4; j++) {
      int idx = tid * 4 + j;
      int ki = idx & 7, tt = (idx >> 3) & 3, b = idx >> 5;
      Zb[(ki * 4 + 0) * ZPAD + tt * 32 + b] = zr[j].x;
      Zb[(ki * 4 + 1) * ZPAD + tt * 32 + b] = zr[j].y;
      Zb[(ki * 4 + 2) * ZPAD + tt * 32 + b] = zr[j].z;
      Zb[(ki * 4 + 3) * ZPAD + tt * 32 + b] = zr[j].w;
    }
  };

  auto compute = [&](int buf) {
    const float* Wb = Ws + buf * TK * WPAD;
    const float* Zb = Zs + buf * TK * ZPAD;
#pragma unroll 8
    for (int kk = 0; kk < TK; kk++) {
      float4 wa = *reinterpret_cast<const float4*>(Wb + kk * WPAD + trow * 8);
      float4 wb2 = *reinterpret_cast<const float4*>(Wb + kk * WPAD + trow * 8 + 4);
      float4 za = *reinterpret_cast<const float4*>(Zb + kk * ZPAD + tcol * 8);
      float4 zb2 = *reinterpret_cast<const float4*>(Zb + kk * ZPAD + tcol * 8 + 4);
      float w8[8] = {wa.x, wa.y, wa.z, wa.w, wb2.x, wb2.y, wb2.z, wb2.w};
      float z8[8] = {za.x, za.y, za.z, za.w, zb2.x, zb2.y, zb2.z, zb2.w};
#pragma unroll
      for (int i = 0; i < 8; i++)
#pragma unroll
        for (int j = 0; j < 8; j++)
          acc[i][j] = fmaf(w8[i], z8[j], acc[i][j]);
    }
  };

  const int NCH = In / TK;
  ldg_chunk(0);
  sts_chunk(0);
  __syncthreads();
  ldg_chunk(TK);
  for (int c = 0; c < NCH; c++) {
    int buf = c & 1;
    if (c + 1 < NCH) sts_chunk(buf ^ 1);
    if (c + 2 < NCH) ldg_chunk((c + 2) * TK);
    compute(buf);
    __syncthreads();
  }

#pragma unroll
  for (int i = 0; i < 8; i++) {
    int row = r0 + trow * 8 + i;
    float bv = __ldg(bih + row) + __ldg(bhh + row);
    int tt = tcol >> 2;
    int b0 = (tcol & 3) * 8;
    int q = row >> 9, rem = row & 511;
    int clr = rem >> 4, ur = rem & 15;
    float* dst = g_xg + (size_t)(t0 + tt) * XG_T + clr * 2048 + (q * 16 + ur) * 32 + b0;
    float4 v0 = make_float4(acc[i][0] + bv, acc[i][1] + bv, acc[i][2] + bv, acc[i][3] + bv);
    float4 v1 = make_float4(acc[i][4] + bv, acc[i][5] + bv, acc[i][6] + bv, acc[i][7] + bv);
    *reinterpret_cast<float4*>(dst) = v0;
    *reinterpret_cast<float4*>(dst + 4) = v1;
  }
}

__device__ __forceinline__ float fsigm(float v) {
  return __fdividef(1.f, 1.f + __expf(-v));
}
// overflow-safe fast tanh: clamp to +-15 (tanh(+-15)=+-1 in fp32); avoids
// __fdividef(-inf, inf) = NaN for large-negative inputs.
__device__ __forceinline__ float ftanh(float v) {
  v = fminf(15.f, fmaxf(-15.f, v));
  float e = __expf(-2.f * v);
  return __fdividef(1.f - e, 1.f + e);
}

// ============ Wavefront: 4 layer-teams x 32 CTAs, persistent ============
__global__ void __launch_bounds__(WTPB, 1) lstm_wave_kernel(
    const float* __restrict__ h0, const float* __restrict__ c0,
    const float* __restrict__ w_ih, const float* __restrict__ w_hh,
    const float* __restrict__ b_ih, const float* __restrict__ b_hh,
    float* __restrict__ out)
{
  extern __shared__ float smem[];
  float* Wsh = smem + SM_WHH;            // [64][512]
  float* zsh = smem + SM_Z;              // [32][516]  z[b][j]
  float* pre = smem + SM_PRE;            // [2][64][32]; reused as xg partials
  float* wbuf = smem + SM_WBUF;          // [2][64][32] Wih chunk ring (interleaved K-halves)
  float* bsh = smem + SM_BSH;            // [64] next-layer combined bias
  const unsigned wbuf_u32 = smem_u32(wbuf);

  const int tid = threadIdx.x;
  const int ct = blockIdx.x;
  const int team = ct >> 5;              // layer
  const int cl = ct & 31;
  // shared GEMM mapping (rec + xg)
  const int kh = tid >> 8;               // K-half
  const int rg = (tid >> 4) & 15;        // rows rg, +16, +32, +48
  const int bg = tid & 15;               // batches bg, bg+16
  // gates mapping
  const int u = tid >> 5;                // unit 0..15 (warp id)
  const int bb = tid & 31;               // batch (lane)
  const int unit = cl * 16 + u;

  // load Whh slice
  const float* Whh = w_hh + (size_t)team * Gn * Hn;
  for (int idx = tid; idx < 64 * 128; idx += WTPB) {
    int rr = idx >> 7, kk = idx & 127;
    int q = rr >> 4, uu = rr & 15;
    int grb = q * Hn + cl * 16 + uu;
    *reinterpret_cast<float4*>(Wsh + rr * WHP + kk * 4) =
        *reinterpret_cast<const float4*>(Whh + (size_t)grb * Hn + kk * 4);
  }
  float c = c0[(size_t)team * Bn * Hn + (size_t)bb * Hn + unit];

  const float* WihN = w_ih + (size_t)(team + 1) * Gn * In;
  // next-layer combined bias -> smem (once)
  if (team < 3 && tid < 64) {
    int grow = (tid >> 4) * Hn + cl * 16 + (tid & 15);
    bsh[tid] = __ldg(b_ih + (size_t)(team + 1) * Gn + grow) +
               __ldg(b_hh + (size_t)(team + 1) * Gn + grow);
  }

  unsigned* hfl = g_flags + team * 32;
  unsigned* xflp = g_flags + 128 + (team - 1) * 32 + cl;
  unsigned* my_hfl = g_flags + ct;
  unsigned* my_xfl = g_flags + 128 + ct;

  // issue one 8KB interleaved chunk: 64 rows x (16 floats of each K-half)
  auto issue_chunk = [&](int cidx) {
    int row = tid >> 3;                 // 0..63
    int half = (tid >> 2) & 1;          // 0/1
    int f4 = tid & 3;                   // 0..3
    int grow = (row >> 4) * Hn + cl * 16 + (row & 15);
    const char* src = reinterpret_cast<const char*>(
        WihN + (size_t)grow * In + half * 256 + cidx * 16 + f4 * 4);
    unsigned dst = wbuf_u32 +
        (unsigned)(((cidx & 1) * 2048 + row * 32 + half * 16 + f4 * 4) * 4);
    asm volatile("cp.async.cg.shared.global [%0], [%1], 16;" :: "r"(dst), "l"(src));
    asm volatile("cp.async.commit_group;" ::: "memory");
  };

  // stream xg[team+1][tt] from current z (register-accumulated)
  auto xg_stream = [&](int tt) {
    unsigned long long ax[4][2];
#pragma unroll
    for (int i = 0; i < 4; i++) { ax[i][0] = 0ull; ax[i][1] = 0ull; }
#pragma unroll 1
    for (int cc = 0; cc < 16; cc++) {
      asm volatile("cp.async.wait_group 0;" ::: "memory");
      __syncthreads();                   // chunk cc visible; compute(cc-1) done
      if (cc + 1 < 16) issue_chunk(cc + 1);
      const float* wc = wbuf + (cc & 1) * 2048 + kh * 16;
      const float* zp0 = zsh + bg * ZPITCH + kh * 256 + cc * 16;
      const float* zp1 = zp0 + 16 * ZPITCH;
#pragma unroll
      for (int j = 0; j < 16; j += 4) {
        ulonglong2 z0 = *reinterpret_cast<const ulonglong2*>(zp0 + j);
        ulonglong2 z1 = *reinterpret_cast<const ulonglong2*>(zp1 + j);
#pragma unroll
        for (int i = 0; i < 4; i++) {
          ulonglong2 w = *reinterpret_cast<const ulonglong2*>(wc + (rg + 16 * i) * 32 + j);
          FMA2(ax[i][0], w.x, z0.x); FMA2(ax[i][0], w.y, z0.y);
          FMA2(ax[i][1], w.x, z1.x); FMA2(ax[i][1], w.y, z1.y);
        }
      }
    }
    // write K-half partials into pre (dead after gates), reduce, store
#pragma unroll
    for (int i = 0; i < 4; i++) {
      pre[(kh * 64 + rg + 16 * i) * 32 + bg] = f2sum(ax[i][0]);
      pre[(kh * 64 + rg + 16 * i) * 32 + bg + 16] = f2sum(ax[i][1]);
    }
    __syncthreads();
    {
      int r = tid >> 3, b4 = (tid & 7) * 4;
      float4 p0 = *reinterpret_cast<const float4*>(pre + r * 32 + b4);
      float4 p1 = *reinterpret_cast<const float4*>(pre + (64 + r) * 32 + b4);
      float bv = bsh[r];
      float4 o = make_float4(p0.x + p1.x + bv, p0.y + p1.y + bv,
                             p0.z + p1.z + bv, p0.w + p1.w + bv);
      size_t xbase = ((size_t)(team + 1) * Tn + tt) * XG_T + cl * 2048;
      __stcg(reinterpret_cast<float4*>(g_xg + xbase + r * 32 + b4), o);
    }
  };

  float xv0, xv1, xv2, xv3;

  for (int t = 0; t < Tn; t++) {
    // ---- wait: own-team h flags >= t; upstream xg flag >= t+1
    if (t > 0 || team > 0) {
      if (tid < 32) {
        bool ok;
        do {
          ok = true;
          if (t > 0) {
            unsigned v;
            asm volatile("ld.relaxed.gpu.global.b32 %0, [%1];"
                         : "=r"(v) : "l"(hfl + tid) : "memory");
            ok &= (v >= (unsigned)t);
          }
          if (team > 0) {
            unsigned v2;
            asm volatile("ld.relaxed.gpu.global.b32 %0, [%1];"
                         : "=r"(v2) : "l"(xflp) : "memory");
            ok &= (v2 >= (unsigned)(t + 1));
          }
        } while (!__all_sync(0xffffffffu, ok));
        asm volatile("fence.acq_rel.gpu;" ::: "memory");
      }
      __syncthreads();
    }

    // ---- prologue: prefetch first Wih chunk (hidden under stage+rec+gates)
    if (team < 3 && t >= 1) issue_chunk(0);

    // ---- stage z[b][j] = h_{t-1}, prefetch xg[t]
    if (t == 0) {
      const float4* h4 = reinterpret_cast<const float4*>(h0 + (size_t)team * Bn * Hn);
#pragma unroll
      for (int i = 0; i < 8; i++) {      // FULL copy: 4096 float4 = 32 b x 128 jq
        int idx = tid + i * WTPB;
        int b = idx >> 7, jq = idx & 127;
        float4 v = __ldcg(h4 + idx);
        *reinterpret_cast<float4*>(zsh + b * ZPITCH + jq * 4) = v;
      }
    } else {
      const float4* h4 = reinterpret_cast<const float4*>(
          g_h + ((size_t)team * Tn + (t - 1)) * Hn * Bn);   // [j][b]
#pragma unroll
      for (int i = 0; i < 8; i++) {
        int idx = tid + i * WTPB;
        int j = idx >> 3, b4 = (idx & 7) * 4;
        float4 v = __ldcg(h4 + idx);
        zsh[(b4 + 0) * ZPITCH + j] = v.x;
        zsh[(b4 + 1) * ZPITCH + j] = v.y;
        zsh[(b4 + 2) * ZPITCH + j] = v.z;
        zsh[(b4 + 3) * ZPITCH + j] = v.w;
      }
    }
    {
      const float* xp = g_xg + ((size_t)team * Tn + t) * XG_T + cl * 2048 + u * 32 + bb;
      xv0 = __ldcg(xp);
      xv1 = __ldcg(xp + 512);
      xv2 = __ldcg(xp + 1024);
      xv3 = __ldcg(xp + 1536);
    }
    __syncthreads();

    // ---- rec GEMM (f32x2): 4 rows x 2 batches x 256 K per thread
    {
      const float* wr = Wsh + rg * WHP + kh * 256;
      const float* zp = zsh + bg * ZPITCH + kh * 256;
      unsigned long long acc[4][2];
#pragma unroll
      for (int i = 0; i < 4; i++) { acc[i][0] = 0ull; acc[i][1] = 0ull; }
#pragma unroll 4
      for (int k = 0; k < 256; k += 4) {
        ulonglong2 z0 = *reinterpret_cast<const ulonglong2*>(zp + k);
        ulonglong2 z1 = *reinterpret_cast<const ulonglong2*>(zp + 16 * ZPITCH + k);
#pragma unroll
        for (int i = 0; i < 4; i++) {
          ulonglong2 w = *reinterpret_cast<const ulonglong2*>(wr + i * 16 * WHP + k);
          FMA2(acc[i][0], w.x, z0.x); FMA2(acc[i][0], w.y, z0.y);
          FMA2(acc[i][1], w.x, z1.x); FMA2(acc[i][1], w.y, z1.y);
        }
      }
#pragma unroll
      for (int i = 0; i < 4; i++) {
        pre[(kh * 64 + rg + 16 * i) * 32 + bg] = f2sum(acc[i][0]);
        pre[(kh * 64 + rg + 16 * i) * 32 + bg + 16] = f2sum(acc[i][1]);
      }
    }
    __syncthreads();

    // ---- gates + state
    {
      float g0 = xv0 + pre[(0 * 16 + u) * 32 + bb] + pre[(64 + 0 * 16 + u) * 32 + bb];
      float g1 = xv1 + pre[(1 * 16 + u) * 32 + bb] + pre[(64 + 1 * 16 + u) * 32 + bb];
      float g2 = xv2 + pre[(2 * 16 + u) * 32 + bb] + pre[(64 + 2 * 16 + u) * 32 + bb];
      float g3 = xv3 + pre[(3 * 16 + u) * 32 + bb] + pre[(64 + 3 * 16 + u) * 32 + bb];
      float gi = fsigm(g0);
      float gf = fsigm(g1);
      float gg = ftanh(g2);
      float go = fsigm(g3);
      c = gf * c + gi * gg;
      float h = go * ftanh(c);
      __stcg(g_h + ((size_t)team * Tn + t) * Hn * Bn + (size_t)unit * 32 + bb, h);
      if (t == Tn - 1)
        out[(size_t)team * Bn * Hn + (size_t)bb * Hn + unit] = c;
    }
    __syncthreads();
    if (tid == 0) {
      asm volatile("fence.acq_rel.gpu;" ::: "memory");
      asm volatile("st.relaxed.gpu.global.b32 [%0], %1;"
                   :: "l"(my_hfl), "r"((unsigned)(t + 1)) : "memory");
    }

    // ---- xg production for layer team+1, t-1 (uses current z = h_{t-1})
    if (team < 3 && t >= 1) {
      xg_stream(t - 1);
      __syncthreads();
      if (tid == 0) {
        asm volatile("fence.acq_rel.gpu;" ::: "memory");
        asm volatile("st.relaxed.gpu.global.b32 [%0], %1;"
                     :: "l"(my_xfl), "r"((unsigned)t) : "memory");
      }
    }
  }

  // ---- epilogue: produce xg[team+1][2047] from h_2047
  if (team < 3) {
    if (tid < 32) {
      bool ok;
      do {
        unsigned v;
        asm volatile("ld.relaxed.gpu.global.b32 %0, [%1];"
                     : "=r"(v) : "l"(hfl + tid) : "memory");
        ok = (v >= (unsigned)Tn);
      } while (!__all_sync(0xffffffffu, ok));
      asm volatile("fence.acq_rel.gpu;" ::: "memory");
    }
    __syncthreads();
    issue_chunk(0);
    {
      const float4* h4 = reinterpret_cast<const float4*>(
          g_h + ((size_t)team * Tn + (Tn - 1)) * Hn * Bn);
#pragma unroll
      for (int i = 0; i < 8; i++) {
        int idx = tid + i * WTPB;
        int j = idx >> 3, b4 = (idx & 7) * 4;
        float4 v = __ldcg(h4 + idx);
        zsh[(b4 + 0) * ZPITCH + j] = v.x;
        zsh[(b4 + 1) * ZPITCH + j] = v.y;
        zsh[(b4 + 2) * ZPITCH + j] = v.z;
        zsh[(b4 + 3) * ZPITCH + j] = v.w;
      }
    }
    __syncthreads();
    xg_stream(Tn - 1);
    __syncthreads();
    if (tid == 0) {
      asm volatile("fence.acq_rel.gpu;" ::: "memory");
      asm volatile("st.relaxed.gpu.global.b32 [%0], %1;"
                   :: "l"(my_xfl), "r"((unsigned)Tn) : "memory");
    }
  }
}

extern "C" void kernel_launch(void* const* d_in, const int* in_sizes, int n_in,
                              void* d_out, int out_size) {
  const float* x    = (const float*)d_in[0];
  const float* h0   = (const float*)d_in[1];
  const float* c0   = (const float*)d_in[2];
  const float* w_ih = (const float*)d_in[3];
  const float* w_hh = (const float*)d_in[4];
  const float* b_ih = (const float*)d_in[5];
  const float* b_hh = (const float*)d_in[6];
  float* out = (float*)d_out;

  cudaFuncSetAttribute(xg_gemm_kernel,
                       cudaFuncAttributeMaxDynamicSharedMemorySize, GEMM_SMEM);
  cudaFuncSetAttribute(lstm_wave_kernel,
                       cudaFuncAttributeMaxDynamicSharedMemorySize, WAVE_SMEM);

  init_kernel<<<1, 256>>>();
  init_kernel<<<1, 256>>>();
  init_kernel<<<1, 256>>>();
  init_kernel<<<1, 256>>>();
  xg_gemm_kernel<<<dim3(Tn / 4, Gn / TR), GT, GEMM_SMEM>>>(w_ih, b_ih, b_hh, x);
  lstm_wave_kernel<<<128, WTPB, WAVE_SMEM>>>(h0, c0, w_ih, w_hh, b_ih, b_hh, out);
}

// round 12
// speedup vs baseline: 2.5495x; 1.1433x over previous
#include <cuda_runtime.h>
#include <math.h>

#define Bn 32
#define Tn 2048
#define In 512
#define Hn 512
#define Ln 4
#define Gn 2048   // 4*H

// ---------------- phase A (layer-0 xg pre-GEMM) ----------------
#define GT 256
#define TR 128
#define TK 32
#define WPAD 132
#define ZPAD 132
#define GEMM_SMEM ((2*TK*WPAD + 2*TK*ZPAD) * 4)

// ---------------- wavefront kernel ----------------
#define WTPB 512
#define WHP 512       // Whh smem pitch (broadcast loads -> no conflicts)
#define ZPITCH 516
#define PP 33         // pre pitch (bank-conflict-free gate reads)
#define XG_T 65536    // floats per (layer,t) block: 32cl * 32b * 64rows
// smem floats: Whh 64*512 | z 32*516 | pre 2*64*33 | wbuf 2*2048 | bsh 64
#define SM_WHH 0
#define SM_Z   (64*WHP)
#define SM_PRE (SM_Z + 32*ZPITCH)
#define SM_WBUF (SM_PRE + 2*64*PP)
#define SM_BSH (SM_WBUF + 2*2048)
#define WAVE_SMEM ((SM_BSH + 64) * 4)

// Static scratch
__device__ float g_xg[(size_t)Ln * Tn * XG_T];        // [l][t][cl][b][64]
__device__ float g_h[(size_t)Ln * Tn * Bn * Hn];      // [l][t][b][j]
__device__ unsigned g_flags[256];                     // [0:128) h, [128:256) xg

__global__ void init_kernel() {
  if (threadIdx.x < 256) g_flags[threadIdx.x] = 0u;
}

#define FMA2(acc, a, b) \
  asm("fma.rn.f32x2 %0, %1, %2, %0;" : "+l"(acc) : "l"(a), "l"(b))

__device__ __forceinline__ float f2sum(unsigned long long v) {
  unsigned lo = (unsigned)v, hi = (unsigned)(v >> 32);
  return __uint_as_float(lo) + __uint_as_float(hi);
}

__device__ __forceinline__ unsigned smem_u32(const void* p) {
  return (unsigned)__cvta_generic_to_shared(p);
}

// ============ Phase A: xg[0][t][cl][b][64] = Wih0 @ x + bias ============
__global__ void __launch_bounds__(GT, 2) xg_gemm_kernel(
    const float* __restrict__ W,
    const float* __restrict__ bih, const float* __restrict__ bhh,
    const float* __restrict__ x)
{
  extern __shared__ float sm[];
  float* Ws = sm;
  float* Zs = sm + 2 * TK * WPAD;

  const int tid = threadIdx.x;
  const int t0 = blockIdx.x * 4;
  const int r0 = blockIdx.y * TR;
  const int trow = tid >> 4;
  const int tcol = tid & 15;

  float acc[8][8];
#pragma unroll
  for (int i = 0; i < 8; i++)
#pragma unroll
    for (int j = 0; j < 8; j++) acc[i][j] = 0.f;

  float4 wr[4], zr[4];

  auto ldg_chunk = [&](int kc) {
#pragma unroll
    for (int j = 0; j < 4; j++) {
      int idx = tid * 4 + j;
      int row = idx >> 3, kq = idx & 7;
      wr[j] = *reinterpret_cast<const float4*>(W + (size_t)(r0 + row) * In + kc + kq * 4);
    }
#pragma unroll
    for (int j = 0; j < 4; j++) {
      int idx = tid * 4 + j;
      int ki = idx & 7, tt = (idx >> 3) & 3, b = idx >> 5;
      zr[j] = *reinterpret_cast<const float4*>(x + ((size_t)b * Tn + t0 + tt) * In + kc + ki * 4);
    }
  };

  auto sts_chunk = [&](int buf) {
    float* Wb = Ws + buf * TK * WPAD;
    float* Zb = Zs + buf * TK * ZPAD;
#pragma unroll
    for (int j = 0; j < 4; j++) {
      int idx = tid * 4 + j;
      int row = idx >> 3, kq = idx & 7;
      Wb[(kq * 4 + 0) * WPAD + row] = wr[j].x;
      Wb[(kq * 4 + 1) * WPAD + row] = wr[j].y;
      Wb[(kq * 4 + 2) * WPAD + row] = wr[j].z;
      Wb[(kq * 4 + 3) * WPAD + row] = wr[j].w;
    }
#pragma unroll
    for (int j = 0; j < 4; j++) {
      int idx = tid * 4 + j;
      int ki = idx & 7, tt = (idx >> 3) & 3, b = idx >> 5;
      Zb[(ki * 4 + 0) * ZPAD + tt * 32 + b] = zr[j].x;
      Zb[(ki * 4 + 1) * ZPAD + tt * 32 + b] = zr[j].y;
      Zb[(ki * 4 + 2) * ZPAD + tt * 32 + b] = zr[j].z;
      Zb[(ki * 4 + 3) * ZPAD + tt * 32 + b] = zr[j].w;
    }
  };

  auto compute = [&](int buf) {
    const float* Wb = Ws + buf * TK * WPAD;
    const float* Zb = Zs + buf * TK * ZPAD;
#pragma unroll 8
    for (int kk = 0; kk < TK; kk++) {
      float4 wa = *reinterpret_cast<const float4*>(Wb + kk * WPAD + trow * 8);
      float4 wb2 = *reinterpret_cast<const float4*>(Wb + kk * WPAD + trow * 8 + 4);
      float4 za = *reinterpret_cast<const float4*>(Zb + kk * ZPAD + tcol * 8);
      float4 zb2 = *reinterpret_cast<const float4*>(Zb + kk * ZPAD + tcol * 8 + 4);
      float w8[8] = {wa.x, wa.y, wa.z, wa.w, wb2.x, wb2.y, wb2.z, wb2.w};
      float z8[8] = {za.x, za.y, za.z, za.w, zb2.x, zb2.y, zb2.z, zb2.w};
#pragma unroll
      for (int i = 0; i < 8; i++)
#pragma unroll
        for (int j = 0; j < 8; j++)
          acc[i][j] = fmaf(w8[i], z8[j], acc[i][j]);
    }
  };

  const int NCH = In / TK;
  ldg_chunk(0);
  sts_chunk(0);
  __syncthreads();
  ldg_chunk(TK);
  for (int c = 0; c < NCH; c++) {
    int buf = c & 1;
    if (c + 1 < NCH) sts_chunk(buf ^ 1);
    if (c + 2 < NCH) ldg_chunk((c + 2) * TK);
    compute(buf);
    __syncthreads();
  }

  // epilogue: [cl][b][64] layout (scatter; phase A runs once)
#pragma unroll
  for (int i = 0; i < 8; i++) {
    int row = r0 + trow * 8 + i;
    float bv = __ldg(bih + row) + __ldg(bhh + row);
    int tt = tcol >> 2;
    int b0 = (tcol & 3) * 8;
    int q = row >> 9, rem = row & 511;
    int clr = rem >> 4, ur = rem & 15;
    float* dst = g_xg + (size_t)(t0 + tt) * XG_T + clr * 2048 + (q * 16 + ur);
#pragma unroll
    for (int j = 0; j < 8; j++)
      dst[(b0 + j) * 64] = acc[i][j] + bv;
  }
}

__device__ __forceinline__ float fsigm(float v) {
  return __fdividef(1.f, 1.f + __expf(-v));
}
// overflow-safe fast tanh (clamp; avoids -inf/inf NaN)
__device__ __forceinline__ float ftanh(float v) {
  v = fminf(15.f, fmaxf(-15.f, v));
  float e = __expf(-2.f * v);
  return __fdividef(1.f - e, 1.f + e);
}

// ============ Wavefront: 4 layer-teams x 32 CTAs, persistent ============
__global__ void __launch_bounds__(WTPB, 1) lstm_wave_kernel(
    const float* __restrict__ h0, const float* __restrict__ c0,
    const float* __restrict__ w_ih, const float* __restrict__ w_hh,
    const float* __restrict__ b_ih, const float* __restrict__ b_hh,
    float* __restrict__ out)
{
  extern __shared__ float smem[];
  float* Wsh = smem + SM_WHH;            // [64][512]
  float* zsh = smem + SM_Z;              // [32][516]  z[b][j]
  float* pre = smem + SM_PRE;            // [2][64][33]; reused as xg partials
  float* wbuf = smem + SM_WBUF;          // [2][64][32] Wih chunk ring
  float* bsh = smem + SM_BSH;            // [64] next-layer combined bias
  const unsigned wbuf_u32 = smem_u32(wbuf);

  const int tid = threadIdx.x;
  const int ct = blockIdx.x;
  const int team = ct >> 5;              // layer
  const int cl = ct & 31;
  // shared GEMM mapping (rec + xg)
  const int kh = tid >> 8;               // K-half
  const int rg = (tid >> 4) & 15;        // rows rg, +16, +32, +48
  const int bg = tid & 15;               // batches bg, bg+16
  // gates mapping: one (unit, batch) per thread
  const int u = tid & 15;                // unit 0..15
  const int bw = tid >> 4;               // batch 0..31
  const int unit = cl * 16 + u;

  // load Whh slice
  const float* Whh = w_hh + (size_t)team * Gn * Hn;
  for (int idx = tid; idx < 64 * 128; idx += WTPB) {
    int rr = idx >> 7, kk = idx & 127;
    int q = rr >> 4, uu = rr & 15;
    int grb = q * Hn + cl * 16 + uu;
    *reinterpret_cast<float4*>(Wsh + rr * WHP + kk * 4) =
        *reinterpret_cast<const float4*>(Whh + (size_t)grb * Hn + kk * 4);
  }
  float c = c0[(size_t)team * Bn * Hn + (size_t)bw * Hn + unit];

  const float* WihN = w_ih + (size_t)(team + 1) * Gn * In;
  if (team < 3 && tid < 64) {
    int grow = (tid >> 4) * Hn + cl * 16 + (tid & 15);
    bsh[tid] = __ldg(b_ih + (size_t)(team + 1) * Gn + grow) +
               __ldg(b_hh + (size_t)(team + 1) * Gn + grow);
  }

  unsigned* hfl = g_flags + team * 32;
  unsigned* xflp = g_flags + 128 + (team - 1) * 32 + cl;
  unsigned* my_hfl = g_flags + ct;
  unsigned* my_xfl = g_flags + 128 + ct;

  // one 8KB interleaved chunk: 64 rows x (16 floats of each K-half)
  auto issue_chunk = [&](int cidx) {
    int row = tid >> 3;
    int half = (tid >> 2) & 1;
    int f4 = tid & 3;
    int grow = (row >> 4) * Hn + cl * 16 + (row & 15);
    const char* src = reinterpret_cast<const char*>(
        WihN + (size_t)grow * In + half * 256 + cidx * 16 + f4 * 4);
    unsigned dst = wbuf_u32 +
        (unsigned)(((cidx & 1) * 2048 + row * 32 + half * 16 + f4 * 4) * 4);
    asm volatile("cp.async.cg.shared.global [%0], [%1], 16;" :: "r"(dst), "l"(src));
    asm volatile("cp.async.commit_group;" ::: "memory");
  };

  // stream xg[team+1][tt] from current z (register-accumulated)
  auto xg_stream = [&](int tt) {
    unsigned long long ax[4][2];
#pragma unroll
    for (int i = 0; i < 4; i++) { ax[i][0] = 0ull; ax[i][1] = 0ull; }
#pragma unroll 1
    for (int cc = 0; cc < 16; cc++) {
      asm volatile("cp.async.wait_group 0;" ::: "memory");
      __syncthreads();
      if (cc + 1 < 16) issue_chunk(cc + 1);
      const float* wc = wbuf + (cc & 1) * 2048 + kh * 16;
      const float* zp0 = zsh + bg * ZPITCH + kh * 256 + cc * 16;
      const float* zp1 = zp0 + 16 * ZPITCH;
#pragma unroll
      for (int j = 0; j < 16; j += 4) {
        ulonglong2 z0 = *reinterpret_cast<const ulonglong2*>(zp0 + j);
        ulonglong2 z1 = *reinterpret_cast<const ulonglong2*>(zp1 + j);
#pragma unroll
        for (int i = 0; i < 4; i++) {
          ulonglong2 w = *reinterpret_cast<const ulonglong2*>(wc + (rg + 16 * i) * 32 + j);
          FMA2(ax[i][0], w.x, z0.x); FMA2(ax[i][0], w.y, z0.y);
          FMA2(ax[i][1], w.x, z1.x); FMA2(ax[i][1], w.y, z1.y);
        }
      }
    }
#pragma unroll
    for (int i = 0; i < 4; i++) {
      pre[(kh * 64 + rg + 16 * i) * PP + bg] = f2sum(ax[i][0]);
      pre[(kh * 64 + rg + 16 * i) * PP + bg + 16] = f2sum(ax[i][1]);
    }
    __syncthreads();
    {
      int b = tid >> 4, r4 = (tid & 15) * 4;
      float4 o;
      float* op = reinterpret_cast<float*>(&o);
#pragma unroll
      for (int i = 0; i < 4; i++)
        op[i] = pre[(r4 + i) * PP + b] + pre[(64 + r4 + i) * PP + b] + bsh[r4 + i];
      size_t xbase = ((size_t)(team + 1) * Tn + tt) * XG_T + cl * 2048;
      __stcg(reinterpret_cast<float4*>(g_xg + xbase + b * 64 + r4), o);
    }
  };

  float xv0, xv1, xv2, xv3;

  for (int t = 0; t < Tn; t++) {
    // ---- wait: own-team h flags >= t; upstream xg flag >= t+1
    if (t > 0 || team > 0) {
      if (tid < 32) {
        bool ok;
        do {
          ok = true;
          if (t > 0) {
            unsigned v;
            asm volatile("ld.relaxed.gpu.global.b32 %0, [%1];"
                         : "=r"(v) : "l"(hfl + tid) : "memory");
            ok &= (v >= (unsigned)t);
          }
          if (team > 0) {
            unsigned v2;
            asm volatile("ld.relaxed.gpu.global.b32 %0, [%1];"
                         : "=r"(v2) : "l"(xflp) : "memory");
            ok &= (v2 >= (unsigned)(t + 1));
          }
        } while (!__all_sync(0xffffffffu, ok));
        asm volatile("fence.acq_rel.gpu;" ::: "memory");
      }
      __syncthreads();
    }

    if (team < 3 && t >= 1) issue_chunk(0);

    // ---- stage z[b][j] = h_{t-1} (pure coalesced copy; both layouts [b][j])
    {
      const float4* h4 = (t == 0)
          ? reinterpret_cast<const float4*>(h0 + (size_t)team * Bn * Hn)
          : reinterpret_cast<const float4*>(
                g_h + ((size_t)team * Tn + (t - 1)) * Bn * Hn);
#pragma unroll
      for (int i = 0; i < 8; i++) {
        int idx = tid + i * WTPB;
        int b = idx >> 7, jq = idx & 127;
        float4 v = __ldcg(h4 + idx);
        *reinterpret_cast<float4*>(zsh + b * ZPITCH + jq * 4) = v;
      }
    }
    {
      const float* xp = g_xg + ((size_t)team * Tn + t) * XG_T + cl * 2048 + bw * 64 + u;
      xv0 = __ldcg(xp);
      xv1 = __ldcg(xp + 16);
      xv2 = __ldcg(xp + 32);
      xv3 = __ldcg(xp + 48);
    }
    __syncthreads();

    // ---- rec GEMM (f32x2): 4 rows x 2 batches x 256 K per thread
    {
      const float* wr = Wsh + rg * WHP + kh * 256;
      const float* zp = zsh + bg * ZPITCH + kh * 256;
      unsigned long long acc[4][2];
#pragma unroll
      for (int i = 0; i < 4; i++) { acc[i][0] = 0ull; acc[i][1] = 0ull; }
#pragma unroll 4
      for (int k = 0; k < 256; k += 4) {
        ulonglong2 z0 = *reinterpret_cast<const ulonglong2*>(zp + k);
        ulonglong2 z1 = *reinterpret_cast<const ulonglong2*>(zp + 16 * ZPITCH + k);
#pragma unroll
        for (int i = 0; i < 4; i++) {
          ulonglong2 w = *reinterpret_cast<const ulonglong2*>(wr + i * 16 * WHP + k);
          FMA2(acc[i][0], w.x, z0.x); FMA2(acc[i][0], w.y, z0.y);
          FMA2(acc[i][1], w.x, z1.x); FMA2(acc[i][1], w.y, z1.y);
        }
      }
#pragma unroll
      for (int i = 0; i < 4; i++) {
        pre[(kh * 64 + rg + 16 * i) * PP + bg] = f2sum(acc[i][0]);
        pre[(kh * 64 + rg + 16 * i) * PP + bg + 16] = f2sum(acc[i][1]);
      }
    }
    __syncthreads();

    // ---- gates + state (one (unit, batch) per thread)
    {
      float g0 = xv0 + pre[(0 * 16 + u) * PP + bw] + pre[(64 + 0 * 16 + u) * PP + bw];
      float g1 = xv1 + pre[(1 * 16 + u) * PP + bw] + pre[(64 + 1 * 16 + u) * PP + bw];
      float g2 = xv2 + pre[(2 * 16 + u) * PP + bw] + pre[(64 + 2 * 16 + u) * PP + bw];
      float g3 = xv3 + pre[(3 * 16 + u) * PP + bw] + pre[(64 + 3 * 16 + u) * PP + bw];
      float gi = fsigm(g0);
      float gf = fsigm(g1);
      float gg = ftanh(g2);
      float go = fsigm(g3);
      c = gf * c + gi * gg;
      float h = go * ftanh(c);
      __stcg(g_h + ((size_t)team * Tn + t) * Bn * Hn + (size_t)bw * Hn + unit, h);
      if (t == Tn - 1)
        out[(size_t)team * Bn * Hn + (size_t)bw * Hn + unit] = c;
    }
    __syncthreads();
    if (tid == 0) {
      asm volatile("fence.acq_rel.gpu;" ::: "memory");
      asm volatile("st.relaxed.gpu.global.b32 [%0], %1;"
                   :: "l"(my_hfl), "r"((unsigned)(t + 1)) : "memory");
    }

    // ---- xg production for layer team+1, t-1 (uses current z = h_{t-1})
    if (team < 3 && t >= 1) {
      xg_stream(t - 1);
      __syncthreads();
      if (tid == 0) {
        asm volatile("fence.acq_rel.gpu;" ::: "memory");
        asm volatile("st.relaxed.gpu.global.b32 [%0], %1;"
                     :: "l"(my_xfl), "r"((unsigned)t) : "memory");
      }
    }
  }

  // ---- epilogue: produce xg[team+1][2047] from h_2047
  if (team < 3) {
    if (tid < 32) {
      bool ok;
      do {
        unsigned v;
        asm volatile("ld.relaxed.gpu.global.b32 %0, [%1];"
                     : "=r"(v) : "l"(hfl + tid) : "memory");
        ok = (v >= (unsigned)Tn);
      } while (!__all_sync(0xffffffffu, ok));
      asm volatile("fence.acq_rel.gpu;" ::: "memory");
    }
    __syncthreads();
    issue_chunk(0);
    {
      const float4* h4 = reinterpret_cast<const float4*>(
          g_h + ((size_t)team * Tn + (Tn - 1)) * Bn * Hn);
#pragma unroll
      for (int i = 0; i < 8; i++) {
        int idx = tid + i * WTPB;
        int b = idx >> 7, jq = idx & 127;
        float4 v = __ldcg(h4 + idx);
        *reinterpret_cast<float4*>(zsh + b * ZPITCH + jq * 4) = v;
      }
    }
    __syncthreads();
    xg_stream(Tn - 1);
    __syncthreads();
    if (tid == 0) {
      asm volatile("fence.acq_rel.gpu;" ::: "memory");
      asm volatile("st.relaxed.gpu.global.b32 [%0], %1;"
                   :: "l"(my_xfl), "r"((unsigned)Tn) : "memory");
    }
  }
}

extern "C" void kernel_launch(void* const* d_in, const int* in_sizes, int n_in,
                              void* d_out, int out_size) {
  const float* x    = (const float*)d_in[0];
  const float* h0   = (const float*)d_in[1];
  const float* c0   = (const float*)d_in[2];
  const float* w_ih = (const float*)d_in[3];
  const float* w_hh = (const float*)d_in[4];
  const float* b_ih = (const float*)d_in[5];
  const float* b_hh = (const float*)d_in[6];
  float* out = (float*)d_out;

  cudaFuncSetAttribute(xg_gemm_kernel,
                       cudaFuncAttributeMaxDynamicSharedMemorySize, GEMM_SMEM);
  cudaFuncSetAttribute(lstm_wave_kernel,
                       cudaFuncAttributeMaxDynamicSharedMemorySize, WAVE_SMEM);

  // our launch #4 = wave kernel (harness prepends ~2 -> ncu -s 5 captures it)
  init_kernel<<<1, 256>>>();
  xg_gemm_kernel<<<dim3(Tn / 4, Gn / TR), GT, GEMM_SMEM>>>(w_ih, b_ih, b_hh, x);
  init_kernel<<<1, 256>>>();
  lstm_wave_kernel<<<128, WTPB, WAVE_SMEM>>>(h0, c0, w_ih, w_hh, b_ih, b_hh, out);
}